// round 13
// baseline (speedup 1.0000x reference)
#include <cuda_runtime.h>
#include <mma.h>
#include <math.h>
#include <stdint.h>

using namespace nvcuda;

#define NN 40000
#define MPAD 40192
#define NR 474
#define E1 100000
#define ET 130000
#define D1 100
#define D2 200
#define K1P 104
#define K2P 208
#define NB 8192
#define EPSV 1e-12f

// ---------------- device scratch ----------------
__device__ __align__(16) float g_entR[NN * K1P];
__device__ __align__(16) float g_WentR[K1P * D2];
__device__ __align__(16) float g_Y1[(size_t)MPAD * 400];   // [n][ts*200 + h*100 + j]
__device__ __align__(16) float g_Y2[(size_t)MPAD * 400];
__device__ __align__(16) float g_x[(size_t)NN * K2P];
__device__ __align__(16) float g_pre[(size_t)MPAD * 208];
__device__ float g_p1[NN * 4];
__device__ float g_p2[NN * 2];
__device__ float g_mask[NN];
__device__ int4  g_edge[ET];
__device__ int   g_rank[ET];
__device__ int   g_cnt[NN];
__device__ int   g_rowptr[NN + 1];
__device__ int   g_csr[ET];
__device__ __align__(16) float g_B1[K1P * 400];
__device__ __align__(16) float g_B2[K2P * 400];
__device__ __align__(16) float g_w1[NR * 200];   // [r][h*100+j] interleaved
__device__ float g_w2[NR * D2];
__device__ __align__(8) float g_q1[NR * 2];      // [r][h] interleaved
__device__ float g_q2[NR];
__device__ float g_u1[4 * D1];
__device__ float g_u2[2 * D2];
__device__ float g_or1[NR * D2];
__device__ float g_oacc[9];

__device__ __forceinline__ unsigned sm_u32(const void* p) {
    unsigned r;
    asm("{.reg .u64 t; cvta.to.shared.u64 t, %1; cvt.u32.u64 %0, t;}" : "=r"(r) : "l"(p));
    return r;
}
#define CPA16(dst, src, pred) \
    asm volatile("cp.async.cg.shared.global [%0], [%1], 16, %2;\n" \
                 :: "r"(dst), "l"(src), "r"((pred) ? 16 : 0))

// ---------------- launch 1: init + u1 + u2 ----------------
__global__ void k_init(const float* __restrict__ att_a, const float* __restrict__ att_a2,
                       const float* __restrict__ out_a, const float* __restrict__ out_a2) {
    int b = blockIdx.x, t = threadIdx.x;
    if (b < 157) {
        int i = b * 256 + t;
        if (i < NN) { g_cnt[i] = 0; g_mask[i] = 0.f; }
    } else if (b < 159) {
        int i = (b - 157) * 256 + t;
        if (i >= 4 * D1) return;
        int v = i / D1, k = i % D1;
        int h = v / 2, ts = v % 2;
        float s = 0.f;
#pragma unroll 4
        for (int j = 0; j < 100; j++)
            s += att_a[(h * 100 + j) * 300 + ts * 100 + k] * att_a2[h * 100 + j];
        g_u1[i] = s;
    } else if (b < 161) {
        int i = (b - 159) * 256 + t;
        if (i >= 2 * D2) return;
        int ts = i / D2, k = i % D2;
        float s = 0.f;
#pragma unroll 4
        for (int j = 0; j < 200; j++)
            s += out_a[j * 600 + ts * 200 + k] * out_a2[j];
        g_u2[i] = s;
    } else {
        if (t < 9) g_oacc[t] = 0.f;
    }
}

// ---------------- launch 2: mega1 ----------------
#define M1_BUILD 508
#define M1_MASK  (M1_BUILD + 32)
#define M1_B1    (M1_MASK + 163)
#define M1_B2    (M1_B1 + 325)
#define M1_WENT  (M1_B2 + 82)
#define M1_W1    (M1_WENT + 371)
#define M1_OR1   (M1_W1 + 371)
#define M1_ORTHO (M1_OR1 + 24)
#define M1_NORM  (M1_ORTHO + 5000)

__global__ void __launch_bounds__(256) k_mega1(
    const int* __restrict__ edge_list, const int* __restrict__ edge_type,
    const int* __restrict__ nhop, const int* __restrict__ batch_inputs,
    const float* __restrict__ emb, const float* __restrict__ rel_emb,
    const float* __restrict__ W_rel, const float* __restrict__ W_ent,
    const float* __restrict__ att_a, const float* __restrict__ out_a,
    float* __restrict__ out) {
    __shared__ float s0[256], s1[256], s2[256];
    int b = blockIdx.x, tid = threadIdx.x;
    if (b < M1_BUILD) {
        int e = b * 256 + tid;
        if (e >= ET) return;
        int t, s, ra, rb;
        if (e < E1) {
            t = edge_list[e]; s = edge_list[E1 + e];
            ra = edge_type[e]; rb = -1;
        } else {
            int i = e - E1;
            t = nhop[i * 4 + 3]; s = nhop[i * 4 + 0];
            ra = nhop[i * 4 + 1]; rb = nhop[i * 4 + 2];
        }
        g_edge[e] = make_int4(t, s, ra, rb);
        g_rank[e] = atomicAdd(&g_cnt[t], 1);
    } else if (b < M1_MASK) {
        int i = (b - M1_BUILD) * 256 + tid;
        if (i < NB) g_mask[batch_inputs[i * 3 + 2]] = 1.0f;
    } else if (b < M1_B1) {
        int i = (b - M1_MASK) * 256 + tid;
        if (i >= K1P * 400) return;
        int k = i / 400, c = i % 400;
        int ts = c / 200, h = (c % 200) / 100, j = c % 100;
        g_B1[i] = (k < D1) ? wmma::__float_to_tf32(att_a[(h * 100 + j) * 300 + ts * 100 + k]) : 0.f;
    } else if (b < M1_B2) {
        int i = (b - M1_B1) * 256 + tid;
        if (i >= K2P * 400) return;
        int k = i / 400, c = i % 400;
        int ts = c / 200, j = c % 200;
        g_B2[i] = (k < D2) ? wmma::__float_to_tf32(out_a[j * 600 + ts * 200 + k]) : 0.f;
    } else if (b < M1_WENT) {
        int i = (b - M1_B2) * 256 + tid;
        if (i >= K1P * D2) return;
        int k = i / D2, d = i % D2;
        g_WentR[i] = (k < D1) ? wmma::__float_to_tf32(W_ent[k * D2 + d]) : 0.f;
    } else if (b < M1_W1) {
        int i = (b - M1_WENT) * 256 + tid;
        if (i >= NR * 200) return;
        int r = i / 200;
        int rem = i % 200;
        int h = rem / 100, j = rem % 100;
        float s = 0.f;
#pragma unroll 4
        for (int k = 0; k < D1; k++)
            s += rel_emb[r * D1 + k] * att_a[(h * 100 + j) * 300 + 200 + k];
        g_w1[i] = s;   // [r][h*100+j]
    } else if (b < M1_OR1) {
        int i = (b - M1_W1) * 256 + tid;
        if (i >= NR * D2) return;
        int r = i / D2, d = i % D2;
        float s = 0.f;
#pragma unroll 4
        for (int k = 0; k < D1; k++) s += rel_emb[r * D1 + k] * W_rel[k * D2 + d];
        g_or1[i] = s;
        out[NN * D2 + i] = s;
    } else if (b < M1_ORTHO) {
        int ob = b - M1_OR1;
        int m = ob >> 3, c = ob & 7;
        const float* base = (m < 2) ? att_a + m * 30000 : out_a;
        int half = (m < 2) ? 15000 : 60000;
        int len = (half + 7) / 8;
        int lo = c * len, hi = min(lo + len, half);
        float a00 = 0.f, a01 = 0.f, a11 = 0.f;
        for (int i = lo + tid; i < hi; i += 256) {
            float x0 = base[i], x1 = base[half + i];
            a00 += x0 * x0; a01 += x0 * x1; a11 += x1 * x1;
        }
        s0[tid] = a00; s1[tid] = a01; s2[tid] = a11;
        __syncthreads();
        for (int o = 128; o; o >>= 1) {
            if (tid < o) { s0[tid] += s0[tid + o]; s1[tid] += s1[tid + o]; s2[tid] += s2[tid + o]; }
            __syncthreads();
        }
        if (tid == 0) {
            atomicAdd(&g_oacc[m * 3 + 0], s0[0]);
            atomicAdd(&g_oacc[m * 3 + 1], s1[0]);
            atomicAdd(&g_oacc[m * 3 + 2], s2[0]);
        }
    } else {
        // norm + entR + p1 fused
        int n = (b - M1_ORTHO) * 8 + (tid >> 5);
        int lane = tid & 31;
        if (n >= NN) return;
        float v[4]; float ss = 0.f;
#pragma unroll
        for (int j = 0; j < 4; j++) {
            int d = lane + 32 * j;
            v[j] = (d < D1) ? emb[n * D1 + d] : 0.f;
            ss += v[j] * v[j];
        }
#pragma unroll
        for (int o = 16; o; o >>= 1) ss += __shfl_xor_sync(0xffffffffu, ss, o);
        float inv = 1.f / fmaxf(sqrtf(ss), EPSV);
#pragma unroll
        for (int j = 0; j < 4; j++) v[j] *= inv;
#pragma unroll
        for (int j = 0; j < 4; j++) {
            int d = lane + 32 * j;
            if (d < D1) g_entR[(size_t)n * K1P + d] = wmma::__float_to_tf32(v[j]);
        }
        if (lane < 4) g_entR[(size_t)n * K1P + D1 + lane] = 0.f;
#pragma unroll
        for (int p = 0; p < 4; p++) {
            float s = 0.f;
#pragma unroll
            for (int j = 0; j < 4; j++) {
                int d = lane + 32 * j;
                if (d < D1) s += v[j] * __ldg(&g_u1[p * D1 + d]);
            }
#pragma unroll
            for (int o = 16; o; o >>= 1) s += __shfl_xor_sync(0xffffffffu, s, o);
            if (lane == 0) g_p1[n * 4 + p] = s;
        }
    }
}

// ============ GEMM variant 1: full-K single-buffer (K=104), BM=128 BN=80 ============
#define KTILE 104
#define ASTR1 108
#define BSTR1 84
#define ASZ1 (128 * ASTR1)
#define BSZ1 (KTILE * BSTR1)
#define SMEM_G1 ((ASZ1 + BSZ1) * 4)

__device__ __forceinline__ void gemm_k104(const float* __restrict__ A, int M,
                                          const float* __restrict__ B, int N,
                                          float* __restrict__ C, int Npad,
                                          int bx, int by, float* sm) {
    float* As = sm;
    float* Bs = sm + ASZ1;
    const int tid = threadIdx.x;
    const int bm = by * 128, bn = bx * 80;
    const int wid = tid >> 5;
    const int wm = (wid >> 1) * 32;
    const int nc = wid & 1;
    const int joff = nc ? 3 : 0;
    const int nb = nc ? 2 : 3;
    unsigned aBase = sm_u32(As), bBase = sm_u32(Bs);

    wmma::fragment<wmma::accumulator, 16, 16, 8, float> c[2][3];
#pragma unroll
    for (int i = 0; i < 2; i++)
#pragma unroll
        for (int j = 0; j < 3; j++) wmma::fill_fragment(c[i][j], 0.f);

#pragma unroll
    for (int q = 0; q < 13; q++) {
        int idx = q * 256 + tid;
        int m = idx / 26, kq = (idx % 26) * 4;
        int gm = bm + m;
        bool p = (gm < M);
        const float* src = p ? &A[(size_t)gm * K1P + kq] : A;
        CPA16(aBase + (unsigned)(m * ASTR1 + kq) * 4u, src, p);
    }
#pragma unroll
    for (int q = 0; q < 9; q++) {
        int idx = q * 256 + tid;
        if (idx < 2080) {
            int k = idx / 20, c4 = (idx % 20) * 4;
            int gn = bn + c4;
            bool p = (gn < N);
            const float* src = p ? &B[(size_t)k * N + gn] : B;
            CPA16(bBase + (unsigned)(k * BSTR1 + c4) * 4u, src, p);
        }
    }
    asm volatile("cp.async.commit_group;\n" ::);
    asm volatile("cp.async.wait_group 0;\n" ::);
    __syncthreads();
#pragma unroll
    for (int s = 0; s < 13; s++) {
        int k8 = s * 8;
        wmma::fragment<wmma::matrix_a, 16, 16, 8, wmma::precision::tf32, wmma::row_major> a0, a1;
        wmma::load_matrix_sync(a0, &As[wm * ASTR1 + k8], ASTR1);
        wmma::load_matrix_sync(a1, &As[(wm + 16) * ASTR1 + k8], ASTR1);
#pragma unroll
        for (int jj = 0; jj < 3; jj++) {
            if (jj < nb) {
                wmma::fragment<wmma::matrix_b, 16, 16, 8, wmma::precision::tf32, wmma::row_major> bf;
                wmma::load_matrix_sync(bf, &Bs[k8 * BSTR1 + (joff + jj) * 16], BSTR1);
                wmma::mma_sync(c[0][jj], a0, bf, c[0][jj]);
                wmma::mma_sync(c[1][jj], a1, bf, c[1][jj]);
            }
        }
    }
#pragma unroll
    for (int i = 0; i < 2; i++) {
        size_t gm = bm + wm + i * 16;
#pragma unroll
        for (int jj = 0; jj < 3; jj++) {
            if (jj < nb) {
                int gn = bn + (joff + jj) * 16;
                if (gn + 16 <= Npad)
                    wmma::store_matrix_sync(&C[gm * Npad + gn], c[i][jj], Npad,
                                            wmma::mem_row_major);
            }
        }
    }
}

// ============ GEMM variant 2: double-buffered BK=32 pipeline, BM=256 BN=80 (K=208) ============
#define ASTR2 44
#define BSTR2 92
#define ASZ2 (256 * ASTR2)
#define BSZ2 (32 * BSTR2)
#define SMEM_G2 ((2 * ASZ2 + 2 * BSZ2) * 4)

__device__ __forceinline__ void gemm2_stage(const float* __restrict__ A, int M, int Kp,
                                            const float* __restrict__ B, int N,
                                            int bm, int bn, int kk,
                                            unsigned aBase, unsigned bBase, int tid) {
#pragma unroll
    for (int q = 0; q < 8; q++) {
        int idx = q * 256 + tid;
        int m = idx >> 3, kq = (idx & 7) * 4;
        int gm = bm + m, gk = kk + kq;
        bool p = (gm < M) && (gk < Kp);
        const float* src = p ? &A[(size_t)gm * Kp + gk] : A;
        CPA16(aBase + (unsigned)(m * ASTR2 + kq) * 4u, src, p);
    }
#pragma unroll
    for (int q = 0; q < 3; q++) {
        int idx = q * 256 + tid;
        if (idx < 640) {
            int k = idx / 20, c4 = (idx % 20) * 4;
            int gk = kk + k, gn = bn + c4;
            bool p = (gk < Kp) && (gn < N);
            const float* src = p ? &B[(size_t)gk * N + gn] : B;
            CPA16(bBase + (unsigned)(k * BSTR2 + c4) * 4u, src, p);
        }
    }
    asm volatile("cp.async.commit_group;\n" ::);
}

__device__ __forceinline__ void gemm_k208(const float* __restrict__ A, int M,
                                          const float* __restrict__ B, int N,
                                          float* __restrict__ C, int Npad,
                                          int bx, int by, float* sm) {
    const int Kp = K2P;
    float* As = sm;
    float* Bs = sm + 2 * ASZ2;
    const int tid = threadIdx.x;
    const int bm = by * 256, bn = bx * 80;
    const int wm = (tid >> 5) * 32;

    wmma::fragment<wmma::accumulator, 16, 16, 8, float> c[2][5];
#pragma unroll
    for (int i = 0; i < 2; i++)
#pragma unroll
        for (int j = 0; j < 5; j++) wmma::fill_fragment(c[i][j], 0.f);

    const int nk8 = Kp >> 3;
    const int nk = (nk8 + 3) >> 2;
    gemm2_stage(A, M, Kp, B, N, bm, bn, 0, sm_u32(As), sm_u32(Bs), tid);

    int buf = 0;
    for (int kt = 0; kt < nk; kt++) {
        asm volatile("cp.async.wait_group 0;\n" ::);
        __syncthreads();
        if (kt + 1 < nk)
            gemm2_stage(A, M, Kp, B, N, bm, bn, (kt + 1) * 32,
                        sm_u32(As + (buf ^ 1) * ASZ2), sm_u32(Bs + (buf ^ 1) * BSZ2), tid);
        const float* Ab = As + buf * ASZ2;
        const float* Bb = Bs + buf * BSZ2;
        int base8 = kt * 4;
#pragma unroll
        for (int s = 0; s < 4; s++) {
            if (base8 + s < nk8) {
                int k8 = s * 8;
                wmma::fragment<wmma::matrix_a, 16, 16, 8, wmma::precision::tf32, wmma::row_major> a0, a1;
                wmma::load_matrix_sync(a0, &Ab[wm * ASTR2 + k8], ASTR2);
                wmma::load_matrix_sync(a1, &Ab[(wm + 16) * ASTR2 + k8], ASTR2);
#pragma unroll
                for (int j = 0; j < 5; j++) {
                    wmma::fragment<wmma::matrix_b, 16, 16, 8, wmma::precision::tf32, wmma::row_major> bf;
                    wmma::load_matrix_sync(bf, &Bb[k8 * BSTR2 + j * 16], BSTR2);
                    wmma::mma_sync(c[0][j], a0, bf, c[0][j]);
                    wmma::mma_sync(c[1][j], a1, bf, c[1][j]);
                }
            }
        }
        buf ^= 1;
    }
#pragma unroll
    for (int i = 0; i < 2; i++) {
        size_t gm = bm + wm + i * 16;
#pragma unroll
        for (int j = 0; j < 5; j++) {
            int gn = bn + j * 16;
            if (gn + 16 <= Npad)
                wmma::store_matrix_sync(&C[gm * Npad + gn], c[i][j], Npad,
                                        wmma::mem_row_major);
        }
    }
}

// ---------------- launch 3: megaA: scan | w2 | q1 | ortho-final ----------------
#define A_W2  372
#define A_Q1  376
#define A_ORT 377

__global__ void __launch_bounds__(256) k_megaA(const float* __restrict__ out_a,
                                               const float* __restrict__ att_a2,
                                               float* __restrict__ out) {
    __shared__ int ws[8];
    int b = blockIdx.x, t = threadIdx.x;
    if (b == 0) {
        const int PER = 157;
        int base = t * PER;
        int s = 0;
        for (int i = 0; i < PER; i++) {
            int idx = base + i;
            if (idx < NN) s += g_cnt[idx];
        }
        int lane = t & 31, w = t >> 5;
        int v = s;
#pragma unroll
        for (int off = 1; off < 32; off <<= 1) {
            int nv = __shfl_up_sync(0xffffffffu, v, off);
            if (lane >= off) v += nv;
        }
        if (lane == 31) ws[w] = v;
        __syncthreads();
        if (w == 0 && lane < 8) {
            int x = ws[lane];
#pragma unroll
            for (int off = 1; off < 8; off <<= 1) {
                int nv = __shfl_up_sync(0x000000ffu, x, off);
                if (lane >= off) x += nv;
            }
            ws[lane] = x;
        }
        __syncthreads();
        int run = v - s + ((w > 0) ? ws[w - 1] : 0);
        for (int i = 0; i < PER; i++) {
            int idx = base + i;
            if (idx < NN) { g_rowptr[idx] = run; run += g_cnt[idx]; }
        }
        if (t == 255) g_rowptr[NN] = run;
    } else if (b < A_W2) {
        int i = (b - 1) * 256 + t;
        if (i >= NR * D2) return;
        int r = i / D2, j = i % D2;
        float s = 0.f;
#pragma unroll 4
        for (int k = 0; k < D2; k++)
            s += g_or1[r * D2 + k] * out_a[j * 600 + 400 + k];
        g_w2[i] = s;
    } else if (b < A_Q1) {
        int i = (b - A_W2) * 256 + t;
        if (i >= 2 * NR) return;
        int r = i >> 1, h = i & 1;
        float s = 0.f;
#pragma unroll 4
        for (int j = 0; j < D1; j++)
            s += g_w1[r * 200 + h * 100 + j] * att_a2[h * 100 + j];
        g_q1[i] = s;   // [r][h]
    } else {
        if (t == 0) {
            float total = 0.f;
#pragma unroll
            for (int m = 0; m < 3; m++) {
                float a00 = g_oacc[m * 3 + 0], a01 = g_oacc[m * 3 + 1], a11 = g_oacc[m * 3 + 2];
                float n0 = fmaxf(sqrtf(a00), EPSV);
                float n1 = fmaxf(sqrtf(a11), EPSV);
                float g00 = a00 / (n0 * n0);
                float g11 = a11 / (n1 * n1);
                float g01 = a01 / (n0 * n1);
                total += 0.01f * ((g00 - 1.f) * (g00 - 1.f) + (g11 - 1.f) * (g11 - 1.f) + 2.f * g01 * g01);
            }
            out[NN * D2 + NR * D2] = total;
        }
    }
}

// ---------------- launch 4: megaB: Y1 GEMM | pre GEMM | fill | q2 ----------------
#define B_Y1   1570
#define B_PRE  (B_Y1 + 942)
#define B_FILL (B_PRE + 508)
#define B_Q2   (B_FILL + 2)

__global__ void __launch_bounds__(256, 2) k_megaB(const float* __restrict__ out_a2) {
    extern __shared__ float dynsm[];
    int b = blockIdx.x, t = threadIdx.x;
    if (b < B_Y1) {
        gemm_k104(g_entR, NN, g_B1, 400, g_Y1, 400, b % 5, b / 5, dynsm);
    } else if (b < B_PRE) {
        int bb = b - B_Y1;
        gemm_k104(g_entR, NN, g_WentR, D2, g_pre, 208, bb % 3, bb / 3, dynsm);
    } else if (b < B_FILL) {
        int e = (b - B_PRE) * 256 + t;
        if (e >= ET) return;
        int tg = g_edge[e].x;
        g_csr[g_rowptr[tg] + g_rank[e]] = e;
    } else {
        int r = (b - B_FILL) * 256 + t;
        if (r >= NR) return;
        float s = 0.f;
#pragma unroll 4
        for (int j = 0; j < D2; j++) s += g_w2[r * D2 + j] * out_a2[j];
        g_q2[r] = s;
    }
}

// ---------------- gather1: ee1 + aggregation + elu + p2 ----------------
__global__ void k_gather1() {
    __shared__ float su2[400];
    for (int i = threadIdx.x; i < 400; i += blockDim.x) su2[i] = g_u2[i];
    __syncthreads();
    int n = (blockIdx.x * blockDim.x + threadIdx.x) >> 5;
    int lane = threadIdx.x & 31;
    if (n >= NN) return;
    int start = g_rowptr[n], end = g_rowptr[n + 1];
    float pt0 = g_p1[n * 4 + 0], pt1 = g_p1[n * 4 + 2];
    const float2* q1v = (const float2*)g_q1;
    float acc[2][4] = {{0.f, 0.f, 0.f, 0.f}, {0.f, 0.f, 0.f, 0.f}};
    float es0 = 0.f, es1 = 0.f;

    int i = start;
    for (; i + 2 <= end; i += 2) {
        int e0 = g_csr[i], e1 = g_csr[i + 1];
        int4 d0 = g_edge[e0], d1 = g_edge[e1];
        float2 qa0 = q1v[d0.z], qa1 = q1v[d1.z];
        float l00 = pt0 + g_p1[d0.y * 4 + 1] + qa0.x;
        float l01 = pt1 + g_p1[d0.y * 4 + 3] + qa0.y;
        float l10 = pt0 + g_p1[d1.y * 4 + 1] + qa1.x;
        float l11 = pt1 + g_p1[d1.y * 4 + 3] + qa1.y;
        if (d0.w >= 0) { float2 qb = q1v[d0.w]; l00 += qb.x; l01 += qb.y; }
        if (d1.w >= 0) { float2 qb = q1v[d1.w]; l10 += qb.x; l11 += qb.y; }
        float ee00 = expf(-((l00 >= 0.f) ? l00 : 0.2f * l00));
        float ee01 = expf(-((l01 >= 0.f) ? l01 : 0.2f * l01));
        float ee10 = expf(-((l10 >= 0.f) ? l10 : 0.2f * l10));
        float ee11 = expf(-((l11 >= 0.f) ? l11 : 0.2f * l11));
        const float* y0 = &g_Y1[(size_t)d0.y * 400 + 200];
        const float* y1 = &g_Y1[(size_t)d1.y * 400 + 200];
        const float* wa0 = &g_w1[d0.z * 200];
        const float* wa1 = &g_w1[d1.z * 200];
#pragma unroll
        for (int j = 0; j < 4; j++) {
            int d = lane + 32 * j;
            if (d < D1) {
                acc[0][j] += ee00 * (y0[d] + wa0[d]) + ee10 * (y1[d] + wa1[d]);
                acc[1][j] += ee01 * (y0[100 + d] + wa0[100 + d]) + ee11 * (y1[100 + d] + wa1[100 + d]);
            }
        }
        if (d0.w >= 0) {
            const float* wb = &g_w1[d0.w * 200];
#pragma unroll
            for (int j = 0; j < 4; j++) {
                int d = lane + 32 * j;
                if (d < D1) { acc[0][j] += ee00 * wb[d]; acc[1][j] += ee01 * wb[100 + d]; }
            }
        }
        if (d1.w >= 0) {
            const float* wb = &g_w1[d1.w * 200];
#pragma unroll
            for (int j = 0; j < 4; j++) {
                int d = lane + 32 * j;
                if (d < D1) { acc[0][j] += ee10 * wb[d]; acc[1][j] += ee11 * wb[100 + d]; }
            }
        }
        es0 += ee00 + ee10; es1 += ee01 + ee11;
    }
    if (i < end) {
        int e = g_csr[i];
        int4 ed = g_edge[e];
        float2 qa = q1v[ed.z];
        float l0 = pt0 + g_p1[ed.y * 4 + 1] + qa.x;
        float l1 = pt1 + g_p1[ed.y * 4 + 3] + qa.y;
        if (ed.w >= 0) { float2 qb = q1v[ed.w]; l0 += qb.x; l1 += qb.y; }
        float ee0 = expf(-((l0 >= 0.f) ? l0 : 0.2f * l0));
        float ee1 = expf(-((l1 >= 0.f) ? l1 : 0.2f * l1));
        const float* ysrc = &g_Y1[(size_t)ed.y * 400 + 200];
        const float* wa = &g_w1[ed.z * 200];
#pragma unroll
        for (int j = 0; j < 4; j++) {
            int d = lane + 32 * j;
            if (d < D1) {
                acc[0][j] += ee0 * (ysrc[d] + wa[d]);
                acc[1][j] += ee1 * (ysrc[100 + d] + wa[100 + d]);
            }
        }
        if (ed.w >= 0) {
            const float* wb = &g_w1[ed.w * 200];
#pragma unroll
            for (int j = 0; j < 4; j++) {
                int d = lane + 32 * j;
                if (d < D1) { acc[0][j] += ee0 * wb[d]; acc[1][j] += ee1 * wb[100 + d]; }
            }
        }
        es0 += ee0; es1 += ee1;
    }

    bool has = (end > start);
    float inv0 = has ? 1.f / es0 : 0.f;
    float inv1 = has ? 1.f / es1 : 0.f;
    float pa = 0.f, pb = 0.f;
#pragma unroll
    for (int j = 0; j < 4; j++) {
        int d = lane + 32 * j;
        if (d < D1) {
            float o0 = 0.f, o1 = 0.f;
            if (has) {
                float v0 = g_Y1[(size_t)n * 400 + d] + acc[0][j] * inv0;
                float v1 = g_Y1[(size_t)n * 400 + 100 + d] + acc[1][j] * inv1;
                o0 = (v0 > 0.f) ? v0 : expm1f(v0);
                o1 = (v1 > 0.f) ? v1 : expm1f(v1);
            }
            g_x[(size_t)n * K2P + d] = wmma::__float_to_tf32(o0);
            g_x[(size_t)n * K2P + 100 + d] = wmma::__float_to_tf32(o1);
            pa += o0 * su2[d] + o1 * su2[100 + d];
            pb += o0 * su2[200 + d] + o1 * su2[300 + d];
        }
    }
    if (lane < 8) g_x[(size_t)n * K2P + 200 + lane] = 0.f;
#pragma unroll
    for (int o = 16; o; o >>= 1) {
        pa += __shfl_xor_sync(0xffffffffu, pa, o);
        pb += __shfl_xor_sync(0xffffffffu, pb, o);
    }
    if (lane == 0) { g_p2[n * 2] = pa; g_p2[n * 2 + 1] = pb; }
}

// ---------------- launch 6: Y2 GEMM (K=208, pipelined BM=256) ----------------
__global__ void __launch_bounds__(256, 2) k_gemmC() {
    extern __shared__ float dynsm[];
    gemm_k208(g_x, NN, g_B2, 400, g_Y2, 400, blockIdx.x % 5, blockIdx.x / 5, dynsm);
}

// ---------------- gather2 + final fused ----------------
__global__ void k_gather2final(float* __restrict__ outp) {
    int n = (blockIdx.x * blockDim.x + threadIdx.x) >> 5;
    int lane = threadIdx.x & 31;
    if (n >= NN) return;
    int start = g_rowptr[n], end = g_rowptr[n + 1];
    float pt = g_p2[n * 2];
    float acc[7] = {0.f, 0.f, 0.f, 0.f, 0.f, 0.f, 0.f};
    float es = 0.f;

    int i = start;
    for (; i + 2 <= end; i += 2) {
        int e0 = g_csr[i], e1 = g_csr[i + 1];
        int4 d0 = g_edge[e0], d1 = g_edge[e1];
        float l0 = pt + g_p2[d0.y * 2 + 1] + g_q2[d0.z];
        float l1 = pt + g_p2[d1.y * 2 + 1] + g_q2[d1.z];
        if (d0.w >= 0) l0 += g_q2[d0.w];
        if (d1.w >= 0) l1 += g_q2[d1.w];
        float ee0 = expf(-((l0 >= 0.f) ? l0 : 0.2f * l0));
        float ee1 = expf(-((l1 >= 0.f) ? l1 : 0.2f * l1));
        const float* y0 = &g_Y2[(size_t)d0.y * 400 + 200];
        const float* y1 = &g_Y2[(size_t)d1.y * 400 + 200];
        const float* wa0 = &g_w2[d0.z * D2];
        const float* wa1 = &g_w2[d1.z * D2];
#pragma unroll
        for (int j = 0; j < 7; j++) {
            int d = lane + 32 * j;
            if (d < D2)
                acc[j] += ee0 * (y0[d] + wa0[d]) + ee1 * (y1[d] + wa1[d]);
        }
        if (d0.w >= 0) {
            const float* wb = &g_w2[d0.w * D2];
#pragma unroll
            for (int j = 0; j < 7; j++) {
                int d = lane + 32 * j;
                if (d < D2) acc[j] += ee0 * wb[d];
            }
        }
        if (d1.w >= 0) {
            const float* wb = &g_w2[d1.w * D2];
#pragma unroll
            for (int j = 0; j < 7; j++) {
                int d = lane + 32 * j;
                if (d < D2) acc[j] += ee1 * wb[d];
            }
        }
        es += ee0 + ee1;
    }
    if (i < end) {
        int e = g_csr[i];
        int4 ed = g_edge[e];
        float l = pt + g_p2[ed.y * 2 + 1] + g_q2[ed.z];
        if (ed.w >= 0) l += g_q2[ed.w];
        float ee = expf(-((l >= 0.f) ? l : 0.2f * l));
        const float* ys = &g_Y2[(size_t)ed.y * 400 + 200];
        const float* wa = &g_w2[ed.z * D2];
#pragma unroll
        for (int j = 0; j < 7; j++) {
            int d = lane + 32 * j;
            if (d < D2) acc[j] += ee * (ys[d] + wa[d]);
        }
        if (ed.w >= 0) {
            const float* wb = &g_w2[ed.w * D2];
#pragma unroll
            for (int j = 0; j < 7; j++) {
                int d = lane + 32 * j;
                if (d < D2) acc[j] += ee * wb[d];
            }
        }
        es += ee;
    }

    bool has = (end > start);
    float inv = has ? 1.f / es : 0.f;
    float msk = g_mask[n];
    float v[7]; float ss = 0.f;
#pragma unroll
    for (int j = 0; j < 7; j++) {
        int d = lane + 32 * j;
        v[j] = 0.f;
        if (d < D2) {
            float h = has ? (g_Y2[(size_t)n * 400 + d] + acc[j] * inv) : 0.f;
            v[j] = g_pre[(size_t)n * 208 + d] + msk * h;
            ss += v[j] * v[j];
        }
    }
#pragma unroll
    for (int o = 16; o; o >>= 1) ss += __shfl_xor_sync(0xffffffffu, ss, o);
    float inv2 = 1.f / fmaxf(sqrtf(ss), EPSV);
#pragma unroll
    for (int j = 0; j < 7; j++) {
        int d = lane + 32 * j;
        if (d < D2) outp[(size_t)n * D2 + d] = v[j] * inv2;
    }
}

// ---------------- launch ----------------
extern "C" void kernel_launch(void* const* d_in, const int* in_sizes, int n_in,
                              void* d_out, int out_size) {
    const int*   edge_list    = (const int*)d_in[0];
    const int*   edge_type    = (const int*)d_in[1];
    const int*   batch_inputs = (const int*)d_in[2];
    const int*   nhop         = (const int*)d_in[3];
    const float* ent_emb      = (const float*)d_in[4];
    const float* rel_emb      = (const float*)d_in[5];
    const float* W_ent        = (const float*)d_in[6];
    const float* W_rel        = (const float*)d_in[7];
    const float* att_a        = (const float*)d_in[8];
    const float* att_a2       = (const float*)d_in[9];
    const float* out_a        = (const float*)d_in[10];
    const float* out_a2       = (const float*)d_in[11];
    float* out = (float*)d_out;

    cudaFuncSetAttribute(k_megaB, cudaFuncAttributeMaxDynamicSharedMemorySize, SMEM_G1);
    cudaFuncSetAttribute(k_gemmC, cudaFuncAttributeMaxDynamicSharedMemorySize, SMEM_G2);

    k_init<<<162, 256>>>(att_a, att_a2, out_a, out_a2);
    k_mega1<<<M1_NORM, 256>>>(edge_list, edge_type, nhop, batch_inputs,
                              ent_emb, rel_emb, W_rel, W_ent, att_a, out_a, out);
    k_megaA<<<A_ORT + 1, 256>>>(out_a, att_a2, out);
    k_megaB<<<B_Q2, 256, SMEM_G1>>>(out_a2);
    k_gather1<<<NN / 8, 256>>>();
    k_gemmC<<<785, 256, SMEM_G2>>>();
    k_gather2final<<<NN / 8, 256>>>(out);
}

// round 14
// speedup vs baseline: 1.1262x; 1.1262x over previous
#include <cuda_runtime.h>
#include <mma.h>
#include <math.h>
#include <stdint.h>

using namespace nvcuda;

#define NN 40000
#define MPAD 40192
#define NR 474
#define E1 100000
#define ET 130000
#define D1 100
#define D2 200
#define K1P 104
#define K2P 208
#define NB 8192
#define EPSV 1e-12f

// ---------------- device scratch ----------------
__device__ __align__(16) float g_entR[NN * K1P];
__device__ __align__(16) float g_WentR[K1P * D2];
__device__ __align__(16) float g_Y1[(size_t)MPAD * 400];
__device__ __align__(16) float g_Y2[(size_t)MPAD * 400];
__device__ __align__(16) float g_x[(size_t)NN * K2P];
__device__ __align__(16) float g_pre[(size_t)MPAD * 208];
__device__ float g_p1[NN * 4];
__device__ float g_p2[NN * 2];
__device__ float g_mask[NN];
__device__ int4  g_edge[ET];
__device__ int   g_rank[ET];
__device__ int   g_cnt[NN];
__device__ int   g_rowptr[NN + 1];
__device__ int   g_csr[ET];
__device__ int   g_scanflag;
__device__ __align__(16) float g_B1[K1P * 400];
__device__ __align__(16) float g_B2[K2P * 400];
__device__ float g_w1[2 * NR * D1];
__device__ float g_w2[NR * D2];
__device__ float g_q1[2 * NR];
__device__ float g_q2[NR];
__device__ float g_u1[4 * D1];
__device__ float g_u2[2 * D2];
__device__ float g_u2r[D2];
__device__ float g_or1[NR * D2];
__device__ float g_oacc[9];

__device__ __forceinline__ unsigned sm_u32(const void* p) {
    unsigned r;
    asm("{.reg .u64 t; cvta.to.shared.u64 t, %1; cvt.u32.u64 %0, t;}" : "=r"(r) : "l"(p));
    return r;
}
#define CPA16(dst, src, pred) \
    asm volatile("cp.async.cg.shared.global [%0], [%1], 16, %2;\n" \
                 :: "r"(dst), "l"(src), "r"((pred) ? 16 : 0))

// ---------------- launch 1: init + u1 + u2 + u2r ----------------
__global__ void k_init(const float* __restrict__ att_a, const float* __restrict__ att_a2,
                       const float* __restrict__ out_a, const float* __restrict__ out_a2) {
    int b = blockIdx.x, t = threadIdx.x;
    if (b < 157) {
        int i = b * 256 + t;
        if (i < NN) { g_cnt[i] = 0; g_mask[i] = 0.f; }
    } else if (b < 159) {
        int i = (b - 157) * 256 + t;
        if (i >= 4 * D1) return;
        int v = i / D1, k = i % D1;
        int h = v / 2, ts = v % 2;
        float s = 0.f;
#pragma unroll 4
        for (int j = 0; j < 100; j++)
            s += att_a[(h * 100 + j) * 300 + ts * 100 + k] * att_a2[h * 100 + j];
        g_u1[i] = s;
    } else if (b < 161) {
        int i = (b - 159) * 256 + t;
        if (i >= 2 * D2) return;
        int ts = i / D2, k = i % D2;
        float s = 0.f;
#pragma unroll 4
        for (int j = 0; j < 200; j++)
            s += out_a[j * 600 + ts * 200 + k] * out_a2[j];
        g_u2[i] = s;
    } else if (b == 161) {
        int k = t;
        if (k >= D2) return;
        float s = 0.f;
#pragma unroll 4
        for (int j = 0; j < 200; j++)
            s += out_a[j * 600 + 400 + k] * out_a2[j];
        g_u2r[k] = s;
    } else {
        if (t < 9) g_oacc[t] = 0.f;
        if (t == 9) g_scanflag = 0;
    }
}

// ---------------- launch 2: mega1 ----------------
#define M1_BUILD 508
#define M1_MASK  (M1_BUILD + 32)
#define M1_B1    (M1_MASK + 163)
#define M1_B2    (M1_B1 + 325)
#define M1_WENT  (M1_B2 + 82)
#define M1_W1    (M1_WENT + 371)
#define M1_OR1   (M1_W1 + 371)
#define M1_ORTHO (M1_OR1 + 24)
#define M1_NORM  (M1_ORTHO + 5000)

__global__ void __launch_bounds__(256) k_mega1(
    const int* __restrict__ edge_list, const int* __restrict__ edge_type,
    const int* __restrict__ nhop, const int* __restrict__ batch_inputs,
    const float* __restrict__ emb, const float* __restrict__ rel_emb,
    const float* __restrict__ W_rel, const float* __restrict__ W_ent,
    const float* __restrict__ att_a, const float* __restrict__ out_a,
    float* __restrict__ out) {
    __shared__ float s0[256], s1[256], s2[256];
    int b = blockIdx.x, tid = threadIdx.x;
    if (b < M1_BUILD) {
        int e = b * 256 + tid;
        if (e >= ET) return;
        int t, s, ra, rb;
        if (e < E1) {
            t = edge_list[e]; s = edge_list[E1 + e];
            ra = edge_type[e]; rb = -1;
        } else {
            int i = e - E1;
            t = nhop[i * 4 + 3]; s = nhop[i * 4 + 0];
            ra = nhop[i * 4 + 1]; rb = nhop[i * 4 + 2];
        }
        g_edge[e] = make_int4(t, s, ra, rb);
        g_rank[e] = atomicAdd(&g_cnt[t], 1);
    } else if (b < M1_MASK) {
        int i = (b - M1_BUILD) * 256 + tid;
        if (i < NB) g_mask[batch_inputs[i * 3 + 2]] = 1.0f;
    } else if (b < M1_B1) {
        int i = (b - M1_MASK) * 256 + tid;
        if (i >= K1P * 400) return;
        int k = i / 400, c = i % 400;
        int ts = c / 200, h = (c % 200) / 100, j = c % 100;
        g_B1[i] = (k < D1) ? wmma::__float_to_tf32(att_a[(h * 100 + j) * 300 + ts * 100 + k]) : 0.f;
    } else if (b < M1_B2) {
        int i = (b - M1_B1) * 256 + tid;
        if (i >= K2P * 400) return;
        int k = i / 400, c = i % 400;
        int ts = c / 200, j = c % 200;
        g_B2[i] = (k < D2) ? wmma::__float_to_tf32(out_a[j * 600 + ts * 200 + k]) : 0.f;
    } else if (b < M1_WENT) {
        int i = (b - M1_B2) * 256 + tid;
        if (i >= K1P * D2) return;
        int k = i / D2, d = i % D2;
        g_WentR[i] = (k < D1) ? wmma::__float_to_tf32(W_ent[k * D2 + d]) : 0.f;
    } else if (b < M1_W1) {
        int i = (b - M1_WENT) * 256 + tid;
        if (i >= 2 * NR * D1) return;
        int h = i / (NR * D1);
        int rem = i % (NR * D1);
        int r = rem / D1, j = rem % D1;
        float s = 0.f;
#pragma unroll 4
        for (int k = 0; k < D1; k++)
            s += rel_emb[r * D1 + k] * att_a[(h * 100 + j) * 300 + 200 + k];
        g_w1[(h * NR + r) * D1 + j] = s;
    } else if (b < M1_OR1) {
        int i = (b - M1_W1) * 256 + tid;
        if (i >= NR * D2) return;
        int r = i / D2, d = i % D2;
        float s = 0.f;
#pragma unroll 4
        for (int k = 0; k < D1; k++) s += rel_emb[r * D1 + k] * W_rel[k * D2 + d];
        g_or1[i] = s;
        out[NN * D2 + i] = s;
    } else if (b < M1_ORTHO) {
        int ob = b - M1_OR1;
        int m = ob >> 3, c = ob & 7;
        const float* base = (m < 2) ? att_a + m * 30000 : out_a;
        int half = (m < 2) ? 15000 : 60000;
        int len = (half + 7) / 8;
        int lo = c * len, hi = min(lo + len, half);
        float a00 = 0.f, a01 = 0.f, a11 = 0.f;
        for (int i = lo + tid; i < hi; i += 256) {
            float x0 = base[i], x1 = base[half + i];
            a00 += x0 * x0; a01 += x0 * x1; a11 += x1 * x1;
        }
        s0[tid] = a00; s1[tid] = a01; s2[tid] = a11;
        __syncthreads();
        for (int o = 128; o; o >>= 1) {
            if (tid < o) { s0[tid] += s0[tid + o]; s1[tid] += s1[tid + o]; s2[tid] += s2[tid + o]; }
            __syncthreads();
        }
        if (tid == 0) {
            atomicAdd(&g_oacc[m * 3 + 0], s0[0]);
            atomicAdd(&g_oacc[m * 3 + 1], s1[0]);
            atomicAdd(&g_oacc[m * 3 + 2], s2[0]);
        }
    } else {
        int n = (b - M1_ORTHO) * 8 + (tid >> 5);
        int lane = tid & 31;
        if (n >= NN) return;
        float v[4]; float ss = 0.f;
#pragma unroll
        for (int j = 0; j < 4; j++) {
            int d = lane + 32 * j;
            v[j] = (d < D1) ? emb[n * D1 + d] : 0.f;
            ss += v[j] * v[j];
        }
#pragma unroll
        for (int o = 16; o; o >>= 1) ss += __shfl_xor_sync(0xffffffffu, ss, o);
        float inv = 1.f / fmaxf(sqrtf(ss), EPSV);
#pragma unroll
        for (int j = 0; j < 4; j++) v[j] *= inv;
#pragma unroll
        for (int j = 0; j < 4; j++) {
            int d = lane + 32 * j;
            if (d < D1) g_entR[(size_t)n * K1P + d] = wmma::__float_to_tf32(v[j]);
        }
        if (lane < 4) g_entR[(size_t)n * K1P + D1 + lane] = 0.f;
#pragma unroll
        for (int p = 0; p < 4; p++) {
            float s = 0.f;
#pragma unroll
            for (int j = 0; j < 4; j++) {
                int d = lane + 32 * j;
                if (d < D1) s += v[j] * __ldg(&g_u1[p * D1 + d]);
            }
#pragma unroll
            for (int o = 16; o; o >>= 1) s += __shfl_xor_sync(0xffffffffu, s, o);
            if (lane == 0) g_p1[n * 4 + p] = s;
        }
    }
}

// ============ GEMM variant 1: full-K single-buffer (K=104), BM=128 BN=80 ============
#define KTILE 104
#define ASTR1 108
#define BSTR1 84
#define ASZ1 (128 * ASTR1)
#define BSZ1 (KTILE * BSTR1)
#define SMEM_G1 ((ASZ1 + BSZ1) * 4)

__device__ __forceinline__ void gemm_k104(const float* __restrict__ A, int M,
                                          const float* __restrict__ B, int N,
                                          float* __restrict__ C, int Npad,
                                          int bx, int by, float* sm) {
    float* As = sm;
    float* Bs = sm + ASZ1;
    const int tid = threadIdx.x;
    const int bm = by * 128, bn = bx * 80;
    const int wid = tid >> 5;
    const int wm = (wid >> 1) * 32;
    const int nc = wid & 1;
    const int joff = nc ? 3 : 0;
    const int nb = nc ? 2 : 3;
    unsigned aBase = sm_u32(As), bBase = sm_u32(Bs);

    wmma::fragment<wmma::accumulator, 16, 16, 8, float> c[2][3];
#pragma unroll
    for (int i = 0; i < 2; i++)
#pragma unroll
        for (int j = 0; j < 3; j++) wmma::fill_fragment(c[i][j], 0.f);

#pragma unroll
    for (int q = 0; q < 13; q++) {
        int idx = q * 256 + tid;
        int m = idx / 26, kq = (idx % 26) * 4;
        int gm = bm + m;
        bool p = (gm < M);
        const float* src = p ? &A[(size_t)gm * K1P + kq] : A;
        CPA16(aBase + (unsigned)(m * ASTR1 + kq) * 4u, src, p);
    }
#pragma unroll
    for (int q = 0; q < 9; q++) {
        int idx = q * 256 + tid;
        if (idx < 2080) {
            int k = idx / 20, c4 = (idx % 20) * 4;
            int gn = bn + c4;
            bool p = (gn < N);
            const float* src = p ? &B[(size_t)k * N + gn] : B;
            CPA16(bBase + (unsigned)(k * BSTR1 + c4) * 4u, src, p);
        }
    }
    asm volatile("cp.async.commit_group;\n" ::);
    asm volatile("cp.async.wait_group 0;\n" ::);
    __syncthreads();
#pragma unroll
    for (int s = 0; s < 13; s++) {
        int k8 = s * 8;
        wmma::fragment<wmma::matrix_a, 16, 16, 8, wmma::precision::tf32, wmma::row_major> a0, a1;
        wmma::load_matrix_sync(a0, &As[wm * ASTR1 + k8], ASTR1);
        wmma::load_matrix_sync(a1, &As[(wm + 16) * ASTR1 + k8], ASTR1);
#pragma unroll
        for (int jj = 0; jj < 3; jj++) {
            if (jj < nb) {
                wmma::fragment<wmma::matrix_b, 16, 16, 8, wmma::precision::tf32, wmma::row_major> bf;
                wmma::load_matrix_sync(bf, &Bs[k8 * BSTR1 + (joff + jj) * 16], BSTR1);
                wmma::mma_sync(c[0][jj], a0, bf, c[0][jj]);
                wmma::mma_sync(c[1][jj], a1, bf, c[1][jj]);
            }
        }
    }
#pragma unroll
    for (int i = 0; i < 2; i++) {
        size_t gm = bm + wm + i * 16;
#pragma unroll
        for (int jj = 0; jj < 3; jj++) {
            if (jj < nb) {
                int gn = bn + (joff + jj) * 16;
                if (gn + 16 <= Npad)
                    wmma::store_matrix_sync(&C[gm * Npad + gn], c[i][jj], Npad,
                                            wmma::mem_row_major);
            }
        }
    }
}

// ============ GEMM variant 2: double-buffered BK=32 pipeline, BM=256 BN=80 (K=208) ============
#define ASTR2 44
#define BSTR2 92
#define ASZ2 (256 * ASTR2)
#define BSZ2 (32 * BSTR2)
#define SMEM_G2 ((2 * ASZ2 + 2 * BSZ2) * 4)

__device__ __forceinline__ void gemm2_stage(const float* __restrict__ A, int M, int Kp,
                                            const float* __restrict__ B, int N,
                                            int bm, int bn, int kk,
                                            unsigned aBase, unsigned bBase, int tid) {
#pragma unroll
    for (int q = 0; q < 8; q++) {
        int idx = q * 256 + tid;
        int m = idx >> 3, kq = (idx & 7) * 4;
        int gm = bm + m, gk = kk + kq;
        bool p = (gm < M) && (gk < Kp);
        const float* src = p ? &A[(size_t)gm * Kp + gk] : A;
        CPA16(aBase + (unsigned)(m * ASTR2 + kq) * 4u, src, p);
    }
#pragma unroll
    for (int q = 0; q < 3; q++) {
        int idx = q * 256 + tid;
        if (idx < 640) {
            int k = idx / 20, c4 = (idx % 20) * 4;
            int gk = kk + k, gn = bn + c4;
            bool p = (gk < Kp) && (gn < N);
            const float* src = p ? &B[(size_t)gk * N + gn] : B;
            CPA16(bBase + (unsigned)(k * BSTR2 + c4) * 4u, src, p);
        }
    }
    asm volatile("cp.async.commit_group;\n" ::);
}

__device__ __forceinline__ void gemm_k208(const float* __restrict__ A, int M,
                                          const float* __restrict__ B, int N,
                                          float* __restrict__ C, int Npad,
                                          int bx, int by, float* sm) {
    const int Kp = K2P;
    float* As = sm;
    float* Bs = sm + 2 * ASZ2;
    const int tid = threadIdx.x;
    const int bm = by * 256, bn = bx * 80;
    const int wm = (tid >> 5) * 32;

    wmma::fragment<wmma::accumulator, 16, 16, 8, float> c[2][5];
#pragma unroll
    for (int i = 0; i < 2; i++)
#pragma unroll
        for (int j = 0; j < 5; j++) wmma::fill_fragment(c[i][j], 0.f);

    const int nk8 = Kp >> 3;
    const int nk = (nk8 + 3) >> 2;
    gemm2_stage(A, M, Kp, B, N, bm, bn, 0, sm_u32(As), sm_u32(Bs), tid);

    int buf = 0;
    for (int kt = 0; kt < nk; kt++) {
        asm volatile("cp.async.wait_group 0;\n" ::);
        __syncthreads();
        if (kt + 1 < nk)
            gemm2_stage(A, M, Kp, B, N, bm, bn, (kt + 1) * 32,
                        sm_u32(As + (buf ^ 1) * ASZ2), sm_u32(Bs + (buf ^ 1) * BSZ2), tid);
        const float* Ab = As + buf * ASZ2;
        const float* Bb = Bs + buf * BSZ2;
        int base8 = kt * 4;
#pragma unroll
        for (int s = 0; s < 4; s++) {
            if (base8 + s < nk8) {
                int k8 = s * 8;
                wmma::fragment<wmma::matrix_a, 16, 16, 8, wmma::precision::tf32, wmma::row_major> a0, a1;
                wmma::load_matrix_sync(a0, &Ab[wm * ASTR2 + k8], ASTR2);
                wmma::load_matrix_sync(a1, &Ab[(wm + 16) * ASTR2 + k8], ASTR2);
#pragma unroll
                for (int j = 0; j < 5; j++) {
                    wmma::fragment<wmma::matrix_b, 16, 16, 8, wmma::precision::tf32, wmma::row_major> bf;
                    wmma::load_matrix_sync(bf, &Bb[k8 * BSTR2 + j * 16], BSTR2);
                    wmma::mma_sync(c[0][j], a0, bf, c[0][j]);
                    wmma::mma_sync(c[1][j], a1, bf, c[1][j]);
                }
            }
        }
        buf ^= 1;
    }
#pragma unroll
    for (int i = 0; i < 2; i++) {
        size_t gm = bm + wm + i * 16;
#pragma unroll
        for (int j = 0; j < 5; j++) {
            int gn = bn + j * 16;
            if (gn + 16 <= Npad)
                wmma::store_matrix_sync(&C[gm * Npad + gn], c[i][j], Npad,
                                        wmma::mem_row_major);
        }
    }
}

// ---------------- launch 3: megaAB: scan | Y1 | pre | w2 | q1 | ortho | q2 | fill ----------------
#define AB_Y1S  1
#define AB_PRE  (AB_Y1S + 1570)
#define AB_W2   (AB_PRE + 942)
#define AB_Q1   (AB_W2 + 371)
#define AB_ORT  (AB_Q1 + 4)
#define AB_Q2   (AB_ORT + 1)
#define AB_FILL (AB_Q2 + 2)
#define AB_END  (AB_FILL + 508)

__global__ void __launch_bounds__(256, 2) k_megaAB(const float* __restrict__ out_a,
                                                   const float* __restrict__ att_a2,
                                                   float* __restrict__ out) {
    extern __shared__ float dynsm[];
    __shared__ int ws[8];
    int b = blockIdx.x, t = threadIdx.x;
    if (b == 0) {
        // exclusive scan of g_cnt -> g_rowptr, then release flag
        const int PER = 157;
        int base = t * PER;
        int s = 0;
        for (int i = 0; i < PER; i++) {
            int idx = base + i;
            if (idx < NN) s += g_cnt[idx];
        }
        int lane = t & 31, w = t >> 5;
        int v = s;
#pragma unroll
        for (int off = 1; off < 32; off <<= 1) {
            int nv = __shfl_up_sync(0xffffffffu, v, off);
            if (lane >= off) v += nv;
        }
        if (lane == 31) ws[w] = v;
        __syncthreads();
        if (w == 0 && lane < 8) {
            int x = ws[lane];
#pragma unroll
            for (int off = 1; off < 8; off <<= 1) {
                int nv = __shfl_up_sync(0x000000ffu, x, off);
                if (lane >= off) x += nv;
            }
            ws[lane] = x;
        }
        __syncthreads();
        int run = v - s + ((w > 0) ? ws[w - 1] : 0);
        for (int i = 0; i < PER; i++) {
            int idx = base + i;
            if (idx < NN) { g_rowptr[idx] = run; run += g_cnt[idx]; }
        }
        if (t == 255) g_rowptr[NN] = run;
        __syncthreads();
        __threadfence();
        if (t == 0) atomicExch(&g_scanflag, 1);
    } else if (b < AB_PRE) {
        int bb = b - AB_Y1S;
        gemm_k104(g_entR, NN, g_B1, 400, g_Y1, 400, bb % 5, bb / 5, dynsm);
    } else if (b < AB_W2) {
        int bb = b - AB_PRE;
        gemm_k104(g_entR, NN, g_WentR, D2, g_pre, 208, bb % 3, bb / 3, dynsm);
    } else if (b < AB_Q1) {
        int i = (b - AB_W2) * 256 + t;
        if (i >= NR * D2) return;
        int r = i / D2, j = i % D2;
        float s = 0.f;
#pragma unroll 4
        for (int k = 0; k < D2; k++)
            s += g_or1[r * D2 + k] * out_a[j * 600 + 400 + k];
        g_w2[i] = s;
    } else if (b < AB_ORT) {
        int i = (b - AB_Q1) * 256 + t;
        if (i >= 2 * NR) return;
        int h = i / NR, r = i % NR;
        float s = 0.f;
#pragma unroll 4
        for (int j = 0; j < D1; j++)
            s += g_w1[(h * NR + r) * D1 + j] * att_a2[h * 100 + j];
        g_q1[i] = s;
    } else if (b < AB_Q2) {
        if (t == 0) {
            float total = 0.f;
#pragma unroll
            for (int m = 0; m < 3; m++) {
                float a00 = g_oacc[m * 3 + 0], a01 = g_oacc[m * 3 + 1], a11 = g_oacc[m * 3 + 2];
                float n0 = fmaxf(sqrtf(a00), EPSV);
                float n1 = fmaxf(sqrtf(a11), EPSV);
                float g00 = a00 / (n0 * n0);
                float g11 = a11 / (n1 * n1);
                float g01 = a01 / (n0 * n1);
                total += 0.01f * ((g00 - 1.f) * (g00 - 1.f) + (g11 - 1.f) * (g11 - 1.f) + 2.f * g01 * g01);
            }
            out[NN * D2 + NR * D2] = total;
        }
    } else if (b < AB_FILL) {
        // q2[r] = sum_k or1[r][k] * u2r[k]   (no dependency on w2)
        int r = (b - AB_Q2) * 256 + t;
        if (r >= NR) return;
        float s = 0.f;
#pragma unroll 4
        for (int k = 0; k < D2; k++) s += g_or1[r * D2 + k] * g_u2r[k];
        g_q2[r] = s;
    } else {
        // fill: wait for scan (block 0, wave 1) to publish rowptr
        if (t == 0) {
            while (((volatile int*)&g_scanflag)[0] == 0) { }
        }
        __syncthreads();
        int e = (b - AB_FILL) * 256 + t;
        if (e >= ET) return;
        int tg = g_edge[e].x;
        int rp = __ldcg(&g_rowptr[tg]);
        g_csr[rp + g_rank[e]] = e;
    }
}

// ---------------- gather1: ee1 + aggregation + elu + p2 (R12 form) ----------------
__global__ void k_gather1() {
    __shared__ float su2[400];
    for (int i = threadIdx.x; i < 400; i += blockDim.x) su2[i] = g_u2[i];
    __syncthreads();
    int n = (blockIdx.x * blockDim.x + threadIdx.x) >> 5;
    int lane = threadIdx.x & 31;
    if (n >= NN) return;
    int start = g_rowptr[n], end = g_rowptr[n + 1];
    float pt0 = g_p1[n * 4 + 0], pt1 = g_p1[n * 4 + 2];
    float acc[2][4] = {{0.f, 0.f, 0.f, 0.f}, {0.f, 0.f, 0.f, 0.f}};
    float es0 = 0.f, es1 = 0.f;

    int i = start;
    for (; i + 2 <= end; i += 2) {
        int e0 = g_csr[i], e1 = g_csr[i + 1];
        int4 d0 = g_edge[e0], d1 = g_edge[e1];
        float sB0 = (d0.w >= 0) ? 1.f : 0.f;
        float sB1 = (d1.w >= 0) ? 1.f : 0.f;
        int rb0 = (d0.w >= 0) ? d0.w : d0.z;
        int rb1 = (d1.w >= 0) ? d1.w : d1.z;
        float l00 = pt0 + g_p1[d0.y * 4 + 1] + g_q1[d0.z] + sB0 * g_q1[rb0];
        float l01 = pt1 + g_p1[d0.y * 4 + 3] + g_q1[NR + d0.z] + sB0 * g_q1[NR + rb0];
        float l10 = pt0 + g_p1[d1.y * 4 + 1] + g_q1[d1.z] + sB1 * g_q1[rb1];
        float l11 = pt1 + g_p1[d1.y * 4 + 3] + g_q1[NR + d1.z] + sB1 * g_q1[NR + rb1];
        float ee00 = expf(-((l00 >= 0.f) ? l00 : 0.2f * l00));
        float ee01 = expf(-((l01 >= 0.f) ? l01 : 0.2f * l01));
        float ee10 = expf(-((l10 >= 0.f) ? l10 : 0.2f * l10));
        float ee11 = expf(-((l11 >= 0.f) ? l11 : 0.2f * l11));
        const float* y0 = &g_Y1[(size_t)d0.y * 400 + 200];
        const float* y1 = &g_Y1[(size_t)d1.y * 400 + 200];
#pragma unroll
        for (int j = 0; j < 4; j++) {
            int d = lane + 32 * j;
            if (d < D1) {
                float v00 = y0[d]       + g_w1[d0.z * D1 + d]        + sB0 * g_w1[rb0 * D1 + d];
                float v01 = y0[100 + d] + g_w1[(NR + d0.z) * D1 + d] + sB0 * g_w1[(NR + rb0) * D1 + d];
                float v10 = y1[d]       + g_w1[d1.z * D1 + d]        + sB1 * g_w1[rb1 * D1 + d];
                float v11 = y1[100 + d] + g_w1[(NR + d1.z) * D1 + d] + sB1 * g_w1[(NR + rb1) * D1 + d];
                acc[0][j] += ee00 * v00 + ee10 * v10;
                acc[1][j] += ee01 * v01 + ee11 * v11;
            }
        }
        es0 += ee00 + ee10; es1 += ee01 + ee11;
    }
    if (i < end) {
        int e = g_csr[i];
        int4 ed = g_edge[e];
        float sB = (ed.w >= 0) ? 1.f : 0.f;
        int rb = (ed.w >= 0) ? ed.w : ed.z;
        float l0 = pt0 + g_p1[ed.y * 4 + 1] + g_q1[ed.z] + sB * g_q1[rb];
        float l1 = pt1 + g_p1[ed.y * 4 + 3] + g_q1[NR + ed.z] + sB * g_q1[NR + rb];
        float ee0 = expf(-((l0 >= 0.f) ? l0 : 0.2f * l0));
        float ee1 = expf(-((l1 >= 0.f) ? l1 : 0.2f * l1));
        const float* ysrc = &g_Y1[(size_t)ed.y * 400 + 200];
#pragma unroll
        for (int j = 0; j < 4; j++) {
            int d = lane + 32 * j;
            if (d < D1) {
                acc[0][j] += ee0 * (ysrc[d]       + g_w1[ed.z * D1 + d]        + sB * g_w1[rb * D1 + d]);
                acc[1][j] += ee1 * (ysrc[100 + d] + g_w1[(NR + ed.z) * D1 + d] + sB * g_w1[(NR + rb) * D1 + d]);
            }
        }
        es0 += ee0; es1 += ee1;
    }

    bool has = (end > start);
    float inv0 = has ? 1.f / es0 : 0.f;
    float inv1 = has ? 1.f / es1 : 0.f;
    float pa = 0.f, pb = 0.f;
#pragma unroll
    for (int j = 0; j < 4; j++) {
        int d = lane + 32 * j;
        if (d < D1) {
            float o0 = 0.f, o1 = 0.f;
            if (has) {
                float v0 = g_Y1[(size_t)n * 400 + d] + acc[0][j] * inv0;
                float v1 = g_Y1[(size_t)n * 400 + 100 + d] + acc[1][j] * inv1;
                o0 = (v0 > 0.f) ? v0 : expm1f(v0);
                o1 = (v1 > 0.f) ? v1 : expm1f(v1);
            }
            g_x[(size_t)n * K2P + d] = wmma::__float_to_tf32(o0);
            g_x[(size_t)n * K2P + 100 + d] = wmma::__float_to_tf32(o1);
            pa += o0 * su2[d] + o1 * su2[100 + d];
            pb += o0 * su2[200 + d] + o1 * su2[300 + d];
        }
    }
    if (lane < 8) g_x[(size_t)n * K2P + 200 + lane] = 0.f;
#pragma unroll
    for (int o = 16; o; o >>= 1) {
        pa += __shfl_xor_sync(0xffffffffu, pa, o);
        pb += __shfl_xor_sync(0xffffffffu, pb, o);
    }
    if (lane == 0) { g_p2[n * 2] = pa; g_p2[n * 2 + 1] = pb; }
}

// ---------------- launch 5: Y2 GEMM ----------------
__global__ void __launch_bounds__(256, 2) k_gemmC() {
    extern __shared__ float dynsm[];
    gemm_k208(g_x, NN, g_B2, 400, g_Y2, 400, blockIdx.x % 5, blockIdx.x / 5, dynsm);
}

// ---------------- gather2 + final fused (R12 form) ----------------
__global__ void k_gather2final(float* __restrict__ outp) {
    int n = (blockIdx.x * blockDim.x + threadIdx.x) >> 5;
    int lane = threadIdx.x & 31;
    if (n >= NN) return;
    int start = g_rowptr[n], end = g_rowptr[n + 1];
    float pt = g_p2[n * 2];
    float acc[7] = {0.f, 0.f, 0.f, 0.f, 0.f, 0.f, 0.f};
    float es = 0.f;

    int i = start;
    for (; i + 2 <= end; i += 2) {
        int e0 = g_csr[i], e1 = g_csr[i + 1];
        int4 d0 = g_edge[e0], d1 = g_edge[e1];
        float sB0 = (d0.w >= 0) ? 1.f : 0.f;
        float sB1 = (d1.w >= 0) ? 1.f : 0.f;
        int rb0 = (d0.w >= 0) ? d0.w : d0.z;
        int rb1 = (d1.w >= 0) ? d1.w : d1.z;
        float l0 = pt + g_p2[d0.y * 2 + 1] + g_q2[d0.z] + sB0 * g_q2[rb0];
        float l1 = pt + g_p2[d1.y * 2 + 1] + g_q2[d1.z] + sB1 * g_q2[rb1];
        float ee0 = expf(-((l0 >= 0.f) ? l0 : 0.2f * l0));
        float ee1 = expf(-((l1 >= 0.f) ? l1 : 0.2f * l1));
        const float* y0 = &g_Y2[(size_t)d0.y * 400 + 200];
        const float* y1 = &g_Y2[(size_t)d1.y * 400 + 200];
#pragma unroll
        for (int j = 0; j < 7; j++) {
            int d = lane + 32 * j;
            if (d < D2) {
                float v0 = y0[d] + g_w2[d0.z * D2 + d] + sB0 * g_w2[rb0 * D2 + d];
                float v1 = y1[d] + g_w2[d1.z * D2 + d] + sB1 * g_w2[rb1 * D2 + d];
                acc[j] += ee0 * v0 + ee1 * v1;
            }
        }
        es += ee0 + ee1;
    }
    if (i < end) {
        int e = g_csr[i];
        int4 ed = g_edge[e];
        float sB = (ed.w >= 0) ? 1.f : 0.f;
        int rb = (ed.w >= 0) ? ed.w : ed.z;
        float l = pt + g_p2[ed.y * 2 + 1] + g_q2[ed.z] + sB * g_q2[rb];
        float ee = expf(-((l >= 0.f) ? l : 0.2f * l));
        const float* ys = &g_Y2[(size_t)ed.y * 400 + 200];
#pragma unroll
        for (int j = 0; j < 7; j++) {
            int d = lane + 32 * j;
            if (d < D2)
                acc[j] += ee * (ys[d] + g_w2[ed.z * D2 + d] + sB * g_w2[rb * D2 + d]);
        }
        es += ee;
    }

    bool has = (end > start);
    float inv = has ? 1.f / es : 0.f;
    float msk = g_mask[n];
    float v[7]; float ss = 0.f;
#pragma unroll
    for (int j = 0; j < 7; j++) {
        int d = lane + 32 * j;
        v[j] = 0.f;
        if (d < D2) {
            float h = has ? (g_Y2[(size_t)n * 400 + d] + acc[j] * inv) : 0.f;
            v[j] = g_pre[(size_t)n * 208 + d] + msk * h;
            ss += v[j] * v[j];
        }
    }
#pragma unroll
    for (int o = 16; o; o >>= 1) ss += __shfl_xor_sync(0xffffffffu, ss, o);
    float inv2 = 1.f / fmaxf(sqrtf(ss), EPSV);
#pragma unroll
    for (int j = 0; j < 7; j++) {
        int d = lane + 32 * j;
        if (d < D2) outp[(size_t)n * D2 + d] = v[j] * inv2;
    }
}

// ---------------- launch ----------------
extern "C" void kernel_launch(void* const* d_in, const int* in_sizes, int n_in,
                              void* d_out, int out_size) {
    const int*   edge_list    = (const int*)d_in[0];
    const int*   edge_type    = (const int*)d_in[1];
    const int*   batch_inputs = (const int*)d_in[2];
    const int*   nhop         = (const int*)d_in[3];
    const float* ent_emb      = (const float*)d_in[4];
    const float* rel_emb      = (const float*)d_in[5];
    const float* W_ent        = (const float*)d_in[6];
    const float* W_rel        = (const float*)d_in[7];
    const float* att_a        = (const float*)d_in[8];
    const float* att_a2       = (const float*)d_in[9];
    const float* out_a        = (const float*)d_in[10];
    const float* out_a2       = (const float*)d_in[11];
    float* out = (float*)d_out;

    cudaFuncSetAttribute(k_megaAB, cudaFuncAttributeMaxDynamicSharedMemorySize, SMEM_G1);
    cudaFuncSetAttribute(k_gemmC, cudaFuncAttributeMaxDynamicSharedMemorySize, SMEM_G2);

    k_init<<<163, 256>>>(att_a, att_a2, out_a, out_a2);
    k_mega1<<<M1_NORM, 256>>>(edge_list, edge_type, nhop, batch_inputs,
                              ent_emb, rel_emb, W_rel, W_ent, att_a, out_a, out);
    k_megaAB<<<AB_END, 256, SMEM_G1>>>(out_a, att_a2, out);
    k_gather1<<<NN / 8, 256>>>();
    k_gemmC<<<785, 256, SMEM_G2>>>();
    k_gather2final<<<NN / 8, 256>>>(out);
}

// round 15
// speedup vs baseline: 1.2231x; 1.0861x over previous
#include <cuda_runtime.h>
#include <mma.h>
#include <math.h>
#include <stdint.h>

using namespace nvcuda;

#define NN 40000
#define MPAD 40192
#define NR 474
#define E1 100000
#define ET 130000
#define D1 100
#define D2 200
#define K1P 104
#define K2P 208
#define NB 8192
#define EPSV 1e-12f

// ---------------- device scratch ----------------
__device__ __align__(16) float g_entR[NN * K1P];
__device__ __align__(16) float g_WentR[K1P * D2];
__device__ __align__(16) float g_Y1[(size_t)MPAD * 400];
__device__ __align__(16) float g_Y2[(size_t)MPAD * 400];
__device__ __align__(16) float g_x[(size_t)NN * K2P];
__device__ __align__(16) float g_pre[(size_t)MPAD * 208];
__device__ float g_p1[NN * 4];
__device__ float g_p2[NN * 2];
__device__ float g_mask[NN];
__device__ int4  g_edge[ET];
__device__ int   g_rank[ET];
__device__ int   g_cnt[NN];
__device__ int   g_rowptr[NN + 1];
__device__ int   g_csr[ET];
__device__ int   g_scanflag;
__device__ __align__(16) float g_B1[K1P * 400];
__device__ __align__(16) float g_B2[K2P * 400];
__device__ __align__(16) float g_w1[2 * NR * D1];
__device__ __align__(16) float g_w2[NR * D2];
__device__ float g_q1[2 * NR];
__device__ float g_q2[NR];
__device__ float g_u1[4 * D1];
__device__ float g_u2[2 * D2];
__device__ float g_u2r[D2];
__device__ float g_or1[NR * D2];
__device__ float g_oacc[9];

__device__ __forceinline__ unsigned sm_u32(const void* p) {
    unsigned r;
    asm("{.reg .u64 t; cvta.to.shared.u64 t, %1; cvt.u32.u64 %0, t;}" : "=r"(r) : "l"(p));
    return r;
}
#define CPA16(dst, src, pred) \
    asm volatile("cp.async.cg.shared.global [%0], [%1], 16, %2;\n" \
                 :: "r"(dst), "l"(src), "r"((pred) ? 16 : 0))

__device__ __forceinline__ void acc4(float4& a, float ee, float4 y, float4 wa, float4 wb, float sB) {
    a.x += ee * (y.x + wa.x + sB * wb.x);
    a.y += ee * (y.y + wa.y + sB * wb.y);
    a.z += ee * (y.z + wa.z + sB * wb.z);
    a.w += ee * (y.w + wa.w + sB * wb.w);
}
__device__ __forceinline__ float eluf(float v) { return (v > 0.f) ? v : expm1f(v); }

// ---------------- launch 1: init + u1 + u2 + u2r ----------------
__global__ void k_init(const float* __restrict__ att_a, const float* __restrict__ att_a2,
                       const float* __restrict__ out_a, const float* __restrict__ out_a2) {
    int b = blockIdx.x, t = threadIdx.x;
    if (b < 157) {
        int i = b * 256 + t;
        if (i < NN) { g_cnt[i] = 0; g_mask[i] = 0.f; }
    } else if (b < 159) {
        int i = (b - 157) * 256 + t;
        if (i >= 4 * D1) return;
        int v = i / D1, k = i % D1;
        int h = v / 2, ts = v % 2;
        float s = 0.f;
#pragma unroll 4
        for (int j = 0; j < 100; j++)
            s += att_a[(h * 100 + j) * 300 + ts * 100 + k] * att_a2[h * 100 + j];
        g_u1[i] = s;
    } else if (b < 161) {
        int i = (b - 159) * 256 + t;
        if (i >= 2 * D2) return;
        int ts = i / D2, k = i % D2;
        float s = 0.f;
#pragma unroll 4
        for (int j = 0; j < 200; j++)
            s += out_a[j * 600 + ts * 200 + k] * out_a2[j];
        g_u2[i] = s;
    } else if (b == 161) {
        int k = t;
        if (k >= D2) return;
        float s = 0.f;
#pragma unroll 4
        for (int j = 0; j < 200; j++)
            s += out_a[j * 600 + 400 + k] * out_a2[j];
        g_u2r[k] = s;
    } else {
        if (t < 9) g_oacc[t] = 0.f;
        if (t == 9) g_scanflag = 0;
    }
}

// ---------------- launch 2: mega1 ----------------
#define M1_BUILD 508
#define M1_MASK  (M1_BUILD + 32)
#define M1_B1    (M1_MASK + 163)
#define M1_B2    (M1_B1 + 325)
#define M1_WENT  (M1_B2 + 82)
#define M1_W1    (M1_WENT + 371)
#define M1_OR1   (M1_W1 + 371)
#define M1_ORTHO (M1_OR1 + 24)
#define M1_NORM  (M1_ORTHO + 5000)

__global__ void __launch_bounds__(256) k_mega1(
    const int* __restrict__ edge_list, const int* __restrict__ edge_type,
    const int* __restrict__ nhop, const int* __restrict__ batch_inputs,
    const float* __restrict__ emb, const float* __restrict__ rel_emb,
    const float* __restrict__ W_rel, const float* __restrict__ W_ent,
    const float* __restrict__ att_a, const float* __restrict__ out_a,
    float* __restrict__ out) {
    __shared__ float s0[256], s1[256], s2[256];
    int b = blockIdx.x, tid = threadIdx.x;
    if (b < M1_BUILD) {
        int e = b * 256 + tid;
        if (e >= ET) return;
        int t, s, ra, rb;
        if (e < E1) {
            t = edge_list[e]; s = edge_list[E1 + e];
            ra = edge_type[e]; rb = -1;
        } else {
            int i = e - E1;
            t = nhop[i * 4 + 3]; s = nhop[i * 4 + 0];
            ra = nhop[i * 4 + 1]; rb = nhop[i * 4 + 2];
        }
        g_edge[e] = make_int4(t, s, ra, rb);
        g_rank[e] = atomicAdd(&g_cnt[t], 1);
    } else if (b < M1_MASK) {
        int i = (b - M1_BUILD) * 256 + tid;
        if (i < NB) g_mask[batch_inputs[i * 3 + 2]] = 1.0f;
    } else if (b < M1_B1) {
        int i = (b - M1_MASK) * 256 + tid;
        if (i >= K1P * 400) return;
        int k = i / 400, c = i % 400;
        int ts = c / 200, h = (c % 200) / 100, j = c % 100;
        g_B1[i] = (k < D1) ? wmma::__float_to_tf32(att_a[(h * 100 + j) * 300 + ts * 100 + k]) : 0.f;
    } else if (b < M1_B2) {
        int i = (b - M1_B1) * 256 + tid;
        if (i >= K2P * 400) return;
        int k = i / 400, c = i % 400;
        int ts = c / 200, j = c % 200;
        g_B2[i] = (k < D2) ? wmma::__float_to_tf32(out_a[j * 600 + ts * 200 + k]) : 0.f;
    } else if (b < M1_WENT) {
        int i = (b - M1_B2) * 256 + tid;
        if (i >= K1P * D2) return;
        int k = i / D2, d = i % D2;
        g_WentR[i] = (k < D1) ? wmma::__float_to_tf32(W_ent[k * D2 + d]) : 0.f;
    } else if (b < M1_W1) {
        int i = (b - M1_WENT) * 256 + tid;
        if (i >= 2 * NR * D1) return;
        int h = i / (NR * D1);
        int rem = i % (NR * D1);
        int r = rem / D1, j = rem % D1;
        float s = 0.f;
#pragma unroll 4
        for (int k = 0; k < D1; k++)
            s += rel_emb[r * D1 + k] * att_a[(h * 100 + j) * 300 + 200 + k];
        g_w1[(h * NR + r) * D1 + j] = s;
    } else if (b < M1_OR1) {
        int i = (b - M1_W1) * 256 + tid;
        if (i >= NR * D2) return;
        int r = i / D2, d = i % D2;
        float s = 0.f;
#pragma unroll 4
        for (int k = 0; k < D1; k++) s += rel_emb[r * D1 + k] * W_rel[k * D2 + d];
        g_or1[i] = s;
        out[NN * D2 + i] = s;
    } else if (b < M1_ORTHO) {
        int ob = b - M1_OR1;
        int m = ob >> 3, c = ob & 7;
        const float* base = (m < 2) ? att_a + m * 30000 : out_a;
        int half = (m < 2) ? 15000 : 60000;
        int len = (half + 7) / 8;
        int lo = c * len, hi = min(lo + len, half);
        float a00 = 0.f, a01 = 0.f, a11 = 0.f;
        for (int i = lo + tid; i < hi; i += 256) {
            float x0 = base[i], x1 = base[half + i];
            a00 += x0 * x0; a01 += x0 * x1; a11 += x1 * x1;
        }
        s0[tid] = a00; s1[tid] = a01; s2[tid] = a11;
        __syncthreads();
        for (int o = 128; o; o >>= 1) {
            if (tid < o) { s0[tid] += s0[tid + o]; s1[tid] += s1[tid + o]; s2[tid] += s2[tid + o]; }
            __syncthreads();
        }
        if (tid == 0) {
            atomicAdd(&g_oacc[m * 3 + 0], s0[0]);
            atomicAdd(&g_oacc[m * 3 + 1], s1[0]);
            atomicAdd(&g_oacc[m * 3 + 2], s2[0]);
        }
    } else {
        int n = (b - M1_ORTHO) * 8 + (tid >> 5);
        int lane = tid & 31;
        if (n >= NN) return;
        float v[4]; float ss = 0.f;
#pragma unroll
        for (int j = 0; j < 4; j++) {
            int d = lane + 32 * j;
            v[j] = (d < D1) ? emb[n * D1 + d] : 0.f;
            ss += v[j] * v[j];
        }
#pragma unroll
        for (int o = 16; o; o >>= 1) ss += __shfl_xor_sync(0xffffffffu, ss, o);
        float inv = 1.f / fmaxf(sqrtf(ss), EPSV);
#pragma unroll
        for (int j = 0; j < 4; j++) v[j] *= inv;
#pragma unroll
        for (int j = 0; j < 4; j++) {
            int d = lane + 32 * j;
            if (d < D1) g_entR[(size_t)n * K1P + d] = wmma::__float_to_tf32(v[j]);
        }
        if (lane < 4) g_entR[(size_t)n * K1P + D1 + lane] = 0.f;
#pragma unroll
        for (int p = 0; p < 4; p++) {
            float s = 0.f;
#pragma unroll
            for (int j = 0; j < 4; j++) {
                int d = lane + 32 * j;
                if (d < D1) s += v[j] * __ldg(&g_u1[p * D1 + d]);
            }
#pragma unroll
            for (int o = 16; o; o >>= 1) s += __shfl_xor_sync(0xffffffffu, s, o);
            if (lane == 0) g_p1[n * 4 + p] = s;
        }
    }
}

// ============ GEMM variant 1: full-K single-buffer (K=104), BM=128 BN=80 ============
#define KTILE 104
#define ASTR1 108
#define BSTR1 84
#define ASZ1 (128 * ASTR1)
#define BSZ1 (KTILE * BSTR1)
#define SMEM_G1 ((ASZ1 + BSZ1) * 4)

__device__ __forceinline__ void gemm_k104(const float* __restrict__ A, int M,
                                          const float* __restrict__ B, int N,
                                          float* __restrict__ C, int Npad,
                                          int bx, int by, float* sm) {
    float* As = sm;
    float* Bs = sm + ASZ1;
    const int tid = threadIdx.x;
    const int bm = by * 128, bn = bx * 80;
    const int wid = tid >> 5;
    const int wm = (wid >> 1) * 32;
    const int nc = wid & 1;
    const int joff = nc ? 3 : 0;
    const int nb = nc ? 2 : 3;
    unsigned aBase = sm_u32(As), bBase = sm_u32(Bs);

    wmma::fragment<wmma::accumulator, 16, 16, 8, float> c[2][3];
#pragma unroll
    for (int i = 0; i < 2; i++)
#pragma unroll
        for (int j = 0; j < 3; j++) wmma::fill_fragment(c[i][j], 0.f);

#pragma unroll
    for (int q = 0; q < 13; q++) {
        int idx = q * 256 + tid;
        int m = idx / 26, kq = (idx % 26) * 4;
        int gm = bm + m;
        bool p = (gm < M);
        const float* src = p ? &A[(size_t)gm * K1P + kq] : A;
        CPA16(aBase + (unsigned)(m * ASTR1 + kq) * 4u, src, p);
    }
#pragma unroll
    for (int q = 0; q < 9; q++) {
        int idx = q * 256 + tid;
        if (idx < 2080) {
            int k = idx / 20, c4 = (idx % 20) * 4;
            int gn = bn + c4;
            bool p = (gn < N);
            const float* src = p ? &B[(size_t)k * N + gn] : B;
            CPA16(bBase + (unsigned)(k * BSTR1 + c4) * 4u, src, p);
        }
    }
    asm volatile("cp.async.commit_group;\n" ::);
    asm volatile("cp.async.wait_group 0;\n" ::);
    __syncthreads();
#pragma unroll
    for (int s = 0; s < 13; s++) {
        int k8 = s * 8;
        wmma::fragment<wmma::matrix_a, 16, 16, 8, wmma::precision::tf32, wmma::row_major> a0, a1;
        wmma::load_matrix_sync(a0, &As[wm * ASTR1 + k8], ASTR1);
        wmma::load_matrix_sync(a1, &As[(wm + 16) * ASTR1 + k8], ASTR1);
#pragma unroll
        for (int jj = 0; jj < 3; jj++) {
            if (jj < nb) {
                wmma::fragment<wmma::matrix_b, 16, 16, 8, wmma::precision::tf32, wmma::row_major> bf;
                wmma::load_matrix_sync(bf, &Bs[k8 * BSTR1 + (joff + jj) * 16], BSTR1);
                wmma::mma_sync(c[0][jj], a0, bf, c[0][jj]);
                wmma::mma_sync(c[1][jj], a1, bf, c[1][jj]);
            }
        }
    }
#pragma unroll
    for (int i = 0; i < 2; i++) {
        size_t gm = bm + wm + i * 16;
#pragma unroll
        for (int jj = 0; jj < 3; jj++) {
            if (jj < nb) {
                int gn = bn + (joff + jj) * 16;
                if (gn + 16 <= Npad)
                    wmma::store_matrix_sync(&C[gm * Npad + gn], c[i][jj], Npad,
                                            wmma::mem_row_major);
            }
        }
    }
}

// ============ GEMM variant 2: double-buffered BK=32 pipeline, BM=256 BN=80 (K=208) ============
#define ASTR2 44
#define BSTR2 92
#define ASZ2 (256 * ASTR2)
#define BSZ2 (32 * BSTR2)
#define SMEM_G2 ((2 * ASZ2 + 2 * BSZ2) * 4)

__device__ __forceinline__ void gemm2_stage(const float* __restrict__ A, int M, int Kp,
                                            const float* __restrict__ B, int N,
                                            int bm, int bn, int kk,
                                            unsigned aBase, unsigned bBase, int tid) {
#pragma unroll
    for (int q = 0; q < 8; q++) {
        int idx = q * 256 + tid;
        int m = idx >> 3, kq = (idx & 7) * 4;
        int gm = bm + m, gk = kk + kq;
        bool p = (gm < M) && (gk < Kp);
        const float* src = p ? &A[(size_t)gm * Kp + gk] : A;
        CPA16(aBase + (unsigned)(m * ASTR2 + kq) * 4u, src, p);
    }
#pragma unroll
    for (int q = 0; q < 3; q++) {
        int idx = q * 256 + tid;
        if (idx < 640) {
            int k = idx / 20, c4 = (idx % 20) * 4;
            int gk = kk + k, gn = bn + c4;
            bool p = (gk < Kp) && (gn < N);
            const float* src = p ? &B[(size_t)gk * N + gn] : B;
            CPA16(bBase + (unsigned)(k * BSTR2 + c4) * 4u, src, p);
        }
    }
    asm volatile("cp.async.commit_group;\n" ::);
}

__device__ __forceinline__ void gemm_k208(const float* __restrict__ A, int M,
                                          const float* __restrict__ B, int N,
                                          float* __restrict__ C, int Npad,
                                          int bx, int by, float* sm) {
    const int Kp = K2P;
    float* As = sm;
    float* Bs = sm + 2 * ASZ2;
    const int tid = threadIdx.x;
    const int bm = by * 256, bn = bx * 80;
    const int wm = (tid >> 5) * 32;

    wmma::fragment<wmma::accumulator, 16, 16, 8, float> c[2][5];
#pragma unroll
    for (int i = 0; i < 2; i++)
#pragma unroll
        for (int j = 0; j < 5; j++) wmma::fill_fragment(c[i][j], 0.f);

    const int nk8 = Kp >> 3;
    const int nk = (nk8 + 3) >> 2;
    gemm2_stage(A, M, Kp, B, N, bm, bn, 0, sm_u32(As), sm_u32(Bs), tid);

    int buf = 0;
    for (int kt = 0; kt < nk; kt++) {
        asm volatile("cp.async.wait_group 0;\n" ::);
        __syncthreads();
        if (kt + 1 < nk)
            gemm2_stage(A, M, Kp, B, N, bm, bn, (kt + 1) * 32,
                        sm_u32(As + (buf ^ 1) * ASZ2), sm_u32(Bs + (buf ^ 1) * BSZ2), tid);
        const float* Ab = As + buf * ASZ2;
        const float* Bb = Bs + buf * BSZ2;
        int base8 = kt * 4;
#pragma unroll
        for (int s = 0; s < 4; s++) {
            if (base8 + s < nk8) {
                int k8 = s * 8;
                wmma::fragment<wmma::matrix_a, 16, 16, 8, wmma::precision::tf32, wmma::row_major> a0, a1;
                wmma::load_matrix_sync(a0, &Ab[wm * ASTR2 + k8], ASTR2);
                wmma::load_matrix_sync(a1, &Ab[(wm + 16) * ASTR2 + k8], ASTR2);
#pragma unroll
                for (int j = 0; j < 5; j++) {
                    wmma::fragment<wmma::matrix_b, 16, 16, 8, wmma::precision::tf32, wmma::row_major> bf;
                    wmma::load_matrix_sync(bf, &Bb[k8 * BSTR2 + j * 16], BSTR2);
                    wmma::mma_sync(c[0][j], a0, bf, c[0][j]);
                    wmma::mma_sync(c[1][j], a1, bf, c[1][j]);
                }
            }
        }
        buf ^= 1;
    }
#pragma unroll
    for (int i = 0; i < 2; i++) {
        size_t gm = bm + wm + i * 16;
#pragma unroll
        for (int j = 0; j < 5; j++) {
            int gn = bn + j * 16;
            if (gn + 16 <= Npad)
                wmma::store_matrix_sync(&C[gm * Npad + gn], c[i][j], Npad,
                                        wmma::mem_row_major);
        }
    }
}

// ---------------- launch 3: megaAB ----------------
#define AB_Y1S  1
#define AB_PRE  (AB_Y1S + 1570)
#define AB_W2   (AB_PRE + 942)
#define AB_Q1   (AB_W2 + 371)
#define AB_ORT  (AB_Q1 + 4)
#define AB_Q2   (AB_ORT + 1)
#define AB_FILL (AB_Q2 + 2)
#define AB_END  (AB_FILL + 508)

__global__ void __launch_bounds__(256, 2) k_megaAB(const float* __restrict__ out_a,
                                                   const float* __restrict__ att_a2,
                                                   float* __restrict__ out) {
    extern __shared__ float dynsm[];
    __shared__ int ws[8];
    int b = blockIdx.x, t = threadIdx.x;
    if (b == 0) {
        const int PER = 157;
        int base = t * PER;
        int s = 0;
        for (int i = 0; i < PER; i++) {
            int idx = base + i;
            if (idx < NN) s += g_cnt[idx];
        }
        int lane = t & 31, w = t >> 5;
        int v = s;
#pragma unroll
        for (int off = 1; off < 32; off <<= 1) {
            int nv = __shfl_up_sync(0xffffffffu, v, off);
            if (lane >= off) v += nv;
        }
        if (lane == 31) ws[w] = v;
        __syncthreads();
        if (w == 0 && lane < 8) {
            int x = ws[lane];
#pragma unroll
            for (int off = 1; off < 8; off <<= 1) {
                int nv = __shfl_up_sync(0x000000ffu, x, off);
                if (lane >= off) x += nv;
            }
            ws[lane] = x;
        }
        __syncthreads();
        int run = v - s + ((w > 0) ? ws[w - 1] : 0);
        for (int i = 0; i < PER; i++) {
            int idx = base + i;
            if (idx < NN) { g_rowptr[idx] = run; run += g_cnt[idx]; }
        }
        if (t == 255) g_rowptr[NN] = run;
        __syncthreads();
        __threadfence();
        if (t == 0) atomicExch(&g_scanflag, 1);
    } else if (b < AB_PRE) {
        int bb = b - AB_Y1S;
        gemm_k104(g_entR, NN, g_B1, 400, g_Y1, 400, bb % 5, bb / 5, dynsm);
    } else if (b < AB_W2) {
        int bb = b - AB_PRE;
        gemm_k104(g_entR, NN, g_WentR, D2, g_pre, 208, bb % 3, bb / 3, dynsm);
    } else if (b < AB_Q1) {
        int i = (b - AB_W2) * 256 + t;
        if (i >= NR * D2) return;
        int r = i / D2, j = i % D2;
        float s = 0.f;
#pragma unroll 4
        for (int k = 0; k < D2; k++)
            s += g_or1[r * D2 + k] * out_a[j * 600 + 400 + k];
        g_w2[i] = s;
    } else if (b < AB_ORT) {
        int i = (b - AB_Q1) * 256 + t;
        if (i >= 2 * NR) return;
        int h = i / NR, r = i % NR;
        float s = 0.f;
#pragma unroll 4
        for (int j = 0; j < D1; j++)
            s += g_w1[(h * NR + r) * D1 + j] * att_a2[h * 100 + j];
        g_q1[i] = s;
    } else if (b < AB_Q2) {
        if (t == 0) {
            float total = 0.f;
#pragma unroll
            for (int m = 0; m < 3; m++) {
                float a00 = g_oacc[m * 3 + 0], a01 = g_oacc[m * 3 + 1], a11 = g_oacc[m * 3 + 2];
                float n0 = fmaxf(sqrtf(a00), EPSV);
                float n1 = fmaxf(sqrtf(a11), EPSV);
                float g00 = a00 / (n0 * n0);
                float g11 = a11 / (n1 * n1);
                float g01 = a01 / (n0 * n1);
                total += 0.01f * ((g00 - 1.f) * (g00 - 1.f) + (g11 - 1.f) * (g11 - 1.f) + 2.f * g01 * g01);
            }
            out[NN * D2 + NR * D2] = total;
        }
    } else if (b < AB_FILL) {
        int r = (b - AB_Q2) * 256 + t;
        if (r >= NR) return;
        float s = 0.f;
#pragma unroll 4
        for (int k = 0; k < D2; k++) s += g_or1[r * D2 + k] * g_u2r[k];
        g_q2[r] = s;
    } else {
        if (t == 0) {
            while (((volatile int*)&g_scanflag)[0] == 0) { }
        }
        __syncthreads();
        int e = (b - AB_FILL) * 256 + t;
        if (e >= ET) return;
        int tg = g_edge[e].x;
        int rp = __ldcg(&g_rowptr[tg]);
        g_csr[rp + g_rank[e]] = e;
    }
}

// ---------------- gather1: float4-vectorized ----------------
__global__ void k_gather1() {
    __shared__ __align__(16) float su2s[400];
    for (int i = threadIdx.x; i < 400; i += blockDim.x) su2s[i] = g_u2[i];
    __syncthreads();
    const float4* su2 = (const float4*)su2s;
    int n = (blockIdx.x * blockDim.x + threadIdx.x) >> 5;
    int lane = threadIdx.x & 31;
    if (n >= NN) return;
    int start = g_rowptr[n], end = g_rowptr[n + 1];
    float pt0 = g_p1[n * 4 + 0], pt1 = g_p1[n * 4 + 2];
    const bool act = lane < 25;
    const int f = lane;
    float4 acc0 = {0.f, 0.f, 0.f, 0.f}, acc1 = {0.f, 0.f, 0.f, 0.f};
    float es0 = 0.f, es1 = 0.f;

    int i = start;
    for (; i + 2 <= end; i += 2) {
        int e0 = g_csr[i], e1 = g_csr[i + 1];
        int4 d0 = g_edge[e0], d1 = g_edge[e1];
        float sB0 = (d0.w >= 0) ? 1.f : 0.f;
        float sB1 = (d1.w >= 0) ? 1.f : 0.f;
        int rb0 = (d0.w >= 0) ? d0.w : d0.z;
        int rb1 = (d1.w >= 0) ? d1.w : d1.z;
        float l00 = pt0 + g_p1[d0.y * 4 + 1] + g_q1[d0.z] + sB0 * g_q1[rb0];
        float l01 = pt1 + g_p1[d0.y * 4 + 3] + g_q1[NR + d0.z] + sB0 * g_q1[NR + rb0];
        float l10 = pt0 + g_p1[d1.y * 4 + 1] + g_q1[d1.z] + sB1 * g_q1[rb1];
        float l11 = pt1 + g_p1[d1.y * 4 + 3] + g_q1[NR + d1.z] + sB1 * g_q1[NR + rb1];
        float ee00 = expf(-((l00 >= 0.f) ? l00 : 0.2f * l00));
        float ee01 = expf(-((l01 >= 0.f) ? l01 : 0.2f * l01));
        float ee10 = expf(-((l10 >= 0.f) ? l10 : 0.2f * l10));
        float ee11 = expf(-((l11 >= 0.f) ? l11 : 0.2f * l11));
        if (act) {
            const float4* y0 = (const float4*)&g_Y1[(size_t)d0.y * 400 + 200];
            const float4* y1 = (const float4*)&g_Y1[(size_t)d1.y * 400 + 200];
            acc4(acc0, ee00, y0[f],      ((const float4*)&g_w1[d0.z * D1])[f],        ((const float4*)&g_w1[rb0 * D1])[f],        sB0);
            acc4(acc1, ee01, y0[25 + f], ((const float4*)&g_w1[(NR + d0.z) * D1])[f], ((const float4*)&g_w1[(NR + rb0) * D1])[f], sB0);
            acc4(acc0, ee10, y1[f],      ((const float4*)&g_w1[d1.z * D1])[f],        ((const float4*)&g_w1[rb1 * D1])[f],        sB1);
            acc4(acc1, ee11, y1[25 + f], ((const float4*)&g_w1[(NR + d1.z) * D1])[f], ((const float4*)&g_w1[(NR + rb1) * D1])[f], sB1);
        }
        es0 += ee00 + ee10; es1 += ee01 + ee11;
    }
    if (i < end) {
        int e = g_csr[i];
        int4 ed = g_edge[e];
        float sB = (ed.w >= 0) ? 1.f : 0.f;
        int rb = (ed.w >= 0) ? ed.w : ed.z;
        float l0 = pt0 + g_p1[ed.y * 4 + 1] + g_q1[ed.z] + sB * g_q1[rb];
        float l1 = pt1 + g_p1[ed.y * 4 + 3] + g_q1[NR + ed.z] + sB * g_q1[NR + rb];
        float ee0 = expf(-((l0 >= 0.f) ? l0 : 0.2f * l0));
        float ee1 = expf(-((l1 >= 0.f) ? l1 : 0.2f * l1));
        if (act) {
            const float4* ys = (const float4*)&g_Y1[(size_t)ed.y * 400 + 200];
            acc4(acc0, ee0, ys[f],      ((const float4*)&g_w1[ed.z * D1])[f],        ((const float4*)&g_w1[rb * D1])[f],        sB);
            acc4(acc1, ee1, ys[25 + f], ((const float4*)&g_w1[(NR + ed.z) * D1])[f], ((const float4*)&g_w1[(NR + rb) * D1])[f], sB);
        }
        es0 += ee0; es1 += ee1;
    }

    bool has = (end > start);
    float inv0 = has ? 1.f / es0 : 0.f;
    float inv1 = has ? 1.f / es1 : 0.f;
    float pa = 0.f, pb = 0.f;
    if (act) {
        float4 o0 = {0.f, 0.f, 0.f, 0.f}, o1 = {0.f, 0.f, 0.f, 0.f};
        if (has) {
            const float4* yn = (const float4*)&g_Y1[(size_t)n * 400];
            float4 b0 = yn[f], b1 = yn[25 + f];
            o0.x = eluf(b0.x + acc0.x * inv0); o0.y = eluf(b0.y + acc0.y * inv0);
            o0.z = eluf(b0.z + acc0.z * inv0); o0.w = eluf(b0.w + acc0.w * inv0);
            o1.x = eluf(b1.x + acc1.x * inv1); o1.y = eluf(b1.y + acc1.y * inv1);
            o1.z = eluf(b1.z + acc1.z * inv1); o1.w = eluf(b1.w + acc1.w * inv1);
        }
        float4 s0v, s1v;
        s0v.x = wmma::__float_to_tf32(o0.x); s0v.y = wmma::__float_to_tf32(o0.y);
        s0v.z = wmma::__float_to_tf32(o0.z); s0v.w = wmma::__float_to_tf32(o0.w);
        s1v.x = wmma::__float_to_tf32(o1.x); s1v.y = wmma::__float_to_tf32(o1.y);
        s1v.z = wmma::__float_to_tf32(o1.z); s1v.w = wmma::__float_to_tf32(o1.w);
        ((float4*)&g_x[(size_t)n * K2P])[f] = s0v;
        ((float4*)&g_x[(size_t)n * K2P + 100])[f] = s1v;
        float4 u0 = su2[f], u1 = su2[25 + f], u2a = su2[50 + f], u3 = su2[75 + f];
        pa += o0.x * u0.x + o0.y * u0.y + o0.z * u0.z + o0.w * u0.w
            + o1.x * u1.x + o1.y * u1.y + o1.z * u1.z + o1.w * u1.w;
        pb += o0.x * u2a.x + o0.y * u2a.y + o0.z * u2a.z + o0.w * u2a.w
            + o1.x * u3.x + o1.y * u3.y + o1.z * u3.z + o1.w * u3.w;
    }
    if (lane < 8) g_x[(size_t)n * K2P + 200 + lane] = 0.f;
#pragma unroll
    for (int o = 16; o; o >>= 1) {
        pa += __shfl_xor_sync(0xffffffffu, pa, o);
        pb += __shfl_xor_sync(0xffffffffu, pb, o);
    }
    if (lane == 0) { g_p2[n * 2] = pa; g_p2[n * 2 + 1] = pb; }
}

// ---------------- launch 5: Y2 GEMM ----------------
__global__ void __launch_bounds__(256, 2) k_gemmC() {
    extern __shared__ float dynsm[];
    gemm_k208(g_x, NN, g_B2, 400, g_Y2, 400, blockIdx.x % 5, blockIdx.x / 5, dynsm);
}

// ---------------- gather2 + final fused: float4-vectorized ----------------
__global__ void k_gather2final(float* __restrict__ outp) {
    int n = (blockIdx.x * blockDim.x + threadIdx.x) >> 5;
    int lane = threadIdx.x & 31;
    if (n >= NN) return;
    int start = g_rowptr[n], end = g_rowptr[n + 1];
    float pt = g_p2[n * 2];
    float4 acc[2];
    acc[0] = make_float4(0.f, 0.f, 0.f, 0.f);
    acc[1] = make_float4(0.f, 0.f, 0.f, 0.f);
    float es = 0.f;

    int i = start;
    for (; i + 2 <= end; i += 2) {
        int e0 = g_csr[i], e1 = g_csr[i + 1];
        int4 d0 = g_edge[e0], d1 = g_edge[e1];
        float sB0 = (d0.w >= 0) ? 1.f : 0.f;
        float sB1 = (d1.w >= 0) ? 1.f : 0.f;
        int rb0 = (d0.w >= 0) ? d0.w : d0.z;
        int rb1 = (d1.w >= 0) ? d1.w : d1.z;
        float l0 = pt + g_p2[d0.y * 2 + 1] + g_q2[d0.z] + sB0 * g_q2[rb0];
        float l1 = pt + g_p2[d1.y * 2 + 1] + g_q2[d1.z] + sB1 * g_q2[rb1];
        float ee0 = expf(-((l0 >= 0.f) ? l0 : 0.2f * l0));
        float ee1 = expf(-((l1 >= 0.f) ? l1 : 0.2f * l1));
        const float4* y0 = (const float4*)&g_Y2[(size_t)d0.y * 400 + 200];
        const float4* y1 = (const float4*)&g_Y2[(size_t)d1.y * 400 + 200];
        const float4* wa0 = (const float4*)&g_w2[d0.z * D2];
        const float4* wb0 = (const float4*)&g_w2[rb0 * D2];
        const float4* wa1 = (const float4*)&g_w2[d1.z * D2];
        const float4* wb1 = (const float4*)&g_w2[rb1 * D2];
#pragma unroll
        for (int jj = 0; jj < 2; jj++) {
            int ff = lane + 32 * jj;
            if (ff < 50) {
                acc4(acc[jj], ee0, y0[ff], wa0[ff], wb0[ff], sB0);
                acc4(acc[jj], ee1, y1[ff], wa1[ff], wb1[ff], sB1);
            }
        }
        es += ee0 + ee1;
    }
    if (i < end) {
        int e = g_csr[i];
        int4 ed = g_edge[e];
        float sB = (ed.w >= 0) ? 1.f : 0.f;
        int rb = (ed.w >= 0) ? ed.w : ed.z;
        float l = pt + g_p2[ed.y * 2 + 1] + g_q2[ed.z] + sB * g_q2[rb];
        float ee = expf(-((l >= 0.f) ? l : 0.2f * l));
        const float4* ys = (const float4*)&g_Y2[(size_t)ed.y * 400 + 200];
        const float4* wa = (const float4*)&g_w2[ed.z * D2];
        const float4* wb = (const float4*)&g_w2[rb * D2];
#pragma unroll
        for (int jj = 0; jj < 2; jj++) {
            int ff = lane + 32 * jj;
            if (ff < 50) acc4(acc[jj], ee, ys[ff], wa[ff], wb[ff], sB);
        }
        es += ee;
    }

    bool has = (end > start);
    float inv = has ? 1.f / es : 0.f;
    float msk = g_mask[n];
    float4 v[2];
    float ss = 0.f;
#pragma unroll
    for (int jj = 0; jj < 2; jj++) {
        int ff = lane + 32 * jj;
        v[jj] = make_float4(0.f, 0.f, 0.f, 0.f);
        if (ff < 50) {
            float4 h = make_float4(0.f, 0.f, 0.f, 0.f);
            if (has) {
                float4 bb = ((const float4*)&g_Y2[(size_t)n * 400])[ff];
                h.x = bb.x + acc[jj].x * inv; h.y = bb.y + acc[jj].y * inv;
                h.z = bb.z + acc[jj].z * inv; h.w = bb.w + acc[jj].w * inv;
            }
            float4 pr = ((const float4*)&g_pre[(size_t)n * 208])[ff];
            v[jj].x = pr.x + msk * h.x; v[jj].y = pr.y + msk * h.y;
            v[jj].z = pr.z + msk * h.z; v[jj].w = pr.w + msk * h.w;
            ss += v[jj].x * v[jj].x + v[jj].y * v[jj].y + v[jj].z * v[jj].z + v[jj].w * v[jj].w;
        }
    }
#pragma unroll
    for (int o = 16; o; o >>= 1) ss += __shfl_xor_sync(0xffffffffu, ss, o);
    float inv2 = 1.f / fmaxf(sqrtf(ss), EPSV);
#pragma unroll
    for (int jj = 0; jj < 2; jj++) {
        int ff = lane + 32 * jj;
        if (ff < 50) {
            float4 o4;
            o4.x = v[jj].x * inv2; o4.y = v[jj].y * inv2;
            o4.z = v[jj].z * inv2; o4.w = v[jj].w * inv2;
            ((float4*)&outp[(size_t)n * D2])[ff] = o4;
        }
    }
}

// ---------------- launch ----------------
extern "C" void kernel_launch(void* const* d_in, const int* in_sizes, int n_in,
                              void* d_out, int out_size) {
    const int*   edge_list    = (const int*)d_in[0];
    const int*   edge_type    = (const int*)d_in[1];
    const int*   batch_inputs = (const int*)d_in[2];
    const int*   nhop         = (const int*)d_in[3];
    const float* ent_emb      = (const float*)d_in[4];
    const float* rel_emb      = (const float*)d_in[5];
    const float* W_ent        = (const float*)d_in[6];
    const float* W_rel        = (const float*)d_in[7];
    const float* att_a        = (const float*)d_in[8];
    const float* att_a2       = (const float*)d_in[9];
    const float* out_a        = (const float*)d_in[10];
    const float* out_a2       = (const float*)d_in[11];
    float* out = (float*)d_out;

    cudaFuncSetAttribute(k_megaAB, cudaFuncAttributeMaxDynamicSharedMemorySize, SMEM_G1);
    cudaFuncSetAttribute(k_gemmC, cudaFuncAttributeMaxDynamicSharedMemorySize, SMEM_G2);

    k_init<<<163, 256>>>(att_a, att_a2, out_a, out_a2);
    k_mega1<<<M1_NORM, 256>>>(edge_list, edge_type, nhop, batch_inputs,
                              ent_emb, rel_emb, W_rel, W_ent, att_a, out_a, out);
    k_megaAB<<<AB_END, 256, SMEM_G1>>>(out_a, att_a2, out);
    k_gather1<<<NN / 8, 256>>>();
    k_gemmC<<<785, 256, SMEM_G2>>>();
    k_gather2final<<<NN / 8, 256>>>(out);
}